// round 4
// baseline (speedup 1.0000x reference)
#include <cuda_runtime.h>
#include <cuda_bf16.h>
#include <cstdint>

#define Nn 50000
#define Ee 800000
#define Rr 8
#define Fd 128
#define Hd 128
#define Cc 64
#define RH (Rr * Hd)   // 1024
#define SCANB 512
#define NB ((Nn + SCANB - 1) / SCANB)   // 98

// ---------------- device scratch ----------------
__device__ float         g_agg[(size_t)Nn * RH];   // aggregated features [N, R*F]
__device__ float         g_hA[Nn * Hd];
__device__ float         g_hB[Nn * Hd];
__device__ float         g_qx[Nn * Rr];
__device__ float         g_kx[Nn * Rr];
__device__ __nv_bfloat16 g_Wbh[Hd * RH];   // Wcat [h][r*128+f] hi
__device__ __nv_bfloat16 g_Wbl[Hd * RH];   // lo
__device__ float         g_Wq[Rr * Fd];
__device__ float         g_Wk[Rr * Fd];
__device__ int           g_src[Ee];
__device__ int           g_dst[Ee];
__device__ int           g_et[Ee];
__device__ int           g_esrc[Ee];       // CSR-sorted by dst
__device__ int           g_eet[Ee];
__device__ int           g_rowptr[Nn + 1];
__device__ int           g_rpp[Nn];
__device__ int           g_bsum[NB + 1];
__device__ int           g_cnt[Nn];
__device__ int           g_fill[Nn];
__device__ int           g_is64;

// ---------------- helpers ----------------
__device__ __forceinline__ uint32_t smem_u32(const void* p) {
    uint32_t a;
    asm("{ .reg .u64 t; cvta.to.shared.u64 t, %1; cvt.u32.u64 %0, t; }" : "=r"(a) : "l"(p));
    return a;
}
__device__ __forceinline__ void ldsm_x4(uint32_t* r, uint32_t addr) {
    asm volatile("ldmatrix.sync.aligned.m8n8.x4.shared.b16 {%0,%1,%2,%3}, [%4];"
                 : "=r"(r[0]), "=r"(r[1]), "=r"(r[2]), "=r"(r[3]) : "r"(addr));
}
__device__ __forceinline__ void mma_bf16(float* c, const uint32_t* a, uint32_t b0, uint32_t b1) {
    asm volatile(
        "mma.sync.aligned.m16n8k16.row.col.f32.bf16.bf16.f32 "
        "{%0,%1,%2,%3}, {%4,%5,%6,%7}, {%8,%9}, {%0,%1,%2,%3};"
        : "+f"(c[0]), "+f"(c[1]), "+f"(c[2]), "+f"(c[3])
        : "r"(a[0]), "r"(a[1]), "r"(a[2]), "r"(a[3]), "r"(b0), "r"(b1));
}

// ---------------- dtype detect + edge conversion ----------------
__global__ void detect_kernel(const unsigned* __restrict__ ei) {
    if (threadIdx.x == 0 && blockIdx.x == 0) {
        int zeros = 0;
        for (int i = 0; i < 128; i++)
            if (ei[2 * i + 1] == 0u) zeros++;
        g_is64 = (zeros == 128) ? 1 : 0;
    }
}

__global__ void convert_kernel(const void* __restrict__ ei, const void* __restrict__ et) {
    int e = blockIdx.x * blockDim.x + threadIdx.x;
    if (e >= Ee) return;
    if (g_is64) {
        const long long* p = (const long long*)ei;
        g_src[e] = (int)p[e];
        g_dst[e] = (int)p[Ee + e];
        g_et[e]  = (int)((const long long*)et)[e];
    } else {
        const int* p = (const int*)ei;
        g_src[e] = p[e];
        g_dst[e] = p[Ee + e];
        g_et[e]  = ((const int*)et)[e];
    }
}

// ---------------- CSR build (once; graph shared across layers) ----------------
__global__ void zero_kernel() {
    int i = blockIdx.x * blockDim.x + threadIdx.x;
    if (i < Nn) { g_cnt[i] = 0; g_fill[i] = 0; }
}
__global__ void hist_kernel() {
    int e = blockIdx.x * blockDim.x + threadIdx.x;
    if (e < Ee) atomicAdd(&g_cnt[g_dst[e]], 1);
}
__global__ void scan1_kernel() {
    __shared__ int ss[SCANB];
    int t = threadIdx.x;
    int idx = blockIdx.x * SCANB + t;
    int v = (idx < Nn) ? g_cnt[idx] : 0;
    ss[t] = v;
    __syncthreads();
    for (int off = 1; off < SCANB; off <<= 1) {
        int tmp = (t >= off) ? ss[t - off] : 0;
        __syncthreads();
        ss[t] += tmp;
        __syncthreads();
    }
    if (idx < Nn) g_rpp[idx] = ss[t] - v;       // exclusive within block
    if (t == SCANB - 1) g_bsum[blockIdx.x] = ss[t];
}
__global__ void scan2_kernel() {
    if (threadIdx.x == 0 && blockIdx.x == 0) {
        int total = 0;
        for (int b = 0; b < NB; b++) { int v = g_bsum[b]; g_bsum[b] = total; total += v; }
        g_rowptr[Nn] = total;
    }
}
__global__ void scan3_kernel() {
    int idx = blockIdx.x * blockDim.x + threadIdx.x;
    if (idx < Nn) g_rowptr[idx] = g_rpp[idx] + g_bsum[idx >> 9];
}
__global__ void scatter_kernel() {
    int e = blockIdx.x * blockDim.x + threadIdx.x;
    if (e >= Ee) return;
    int d = g_dst[e];
    int p = g_rowptr[d] + atomicAdd(&g_fill[d], 1);
    g_esrc[p] = g_src[e];
    g_eet[p]  = g_et[e];
}

// ---------------- weight prep ----------------
// Wq[r,f] = sum_h W[r,f,h]*q[h]; Wk likewise. One warp per (r,f).
__global__ void wqk_kernel(const float* __restrict__ W,
                           const float* __restrict__ q,
                           const float* __restrict__ k) {
    int warp = (blockIdx.x * blockDim.x + threadIdx.x) >> 5;
    int lane = threadIdx.x & 31;
    if (warp >= Rr * Fd) return;
    const float* wrow = W + (size_t)warp * Hd;
    float sq = 0.f, sk = 0.f;
#pragma unroll
    for (int j = 0; j < 4; j++) {
        float wv = wrow[lane + 32 * j];
        sq += wv * q[lane + 32 * j];
        sk += wv * k[lane + 32 * j];
    }
#pragma unroll
    for (int o = 16; o; o >>= 1) {
        sq += __shfl_xor_sync(0xffffffffu, sq, o);
        sk += __shfl_xor_sync(0xffffffffu, sk, o);
    }
    if (lane == 0) { g_Wq[warp] = sq; g_Wk[warp] = sk; }
}

// Wcat bf16 hi/lo: g_Wb[h*RH + r*128 + f] = W[r,f,h]
__global__ void wprep_kernel(const float* __restrict__ W) {
    int idx = blockIdx.x * blockDim.x + threadIdx.x;   // over Hd*RH
    if (idx >= Hd * RH) return;
    int kk = idx & (RH - 1);
    int h  = idx >> 10;
    int f  = kk & 127;
    int r  = kk >> 7;
    float v = W[(size_t)r * Fd * Hd + (size_t)f * Hd + h];
    __nv_bfloat16 hi = __float2bfloat16(v);
    __nv_bfloat16 lo = __float2bfloat16(v - __bfloat162float(hi));
    g_Wbh[idx] = hi;
    g_Wbl[idx] = lo;
}

// ---------------- qx/kx: warp per node ----------------
__global__ __launch_bounds__(256) void qxkx_kernel(const float* __restrict__ xin) {
    __shared__ float sq[Rr][Fd], sk[Rr][Fd];
    int tid = threadIdx.x;
    for (int i = tid; i < Rr * Fd; i += 256) {
        sq[i >> 7][i & 127] = g_Wq[i];
        sk[i >> 7][i & 127] = g_Wk[i];
    }
    __syncthreads();
    int w = tid >> 5, lane = tid & 31;
    int n = blockIdx.x * 8 + w;
    float4 xv = *(const float4*)&xin[(size_t)n * Fd + lane * 4];
#pragma unroll
    for (int r = 0; r < Rr; r++) {
        float4 q4 = *(const float4*)&sq[r][lane * 4];
        float4 k4 = *(const float4*)&sk[r][lane * 4];
        float qs = xv.x * q4.x + xv.y * q4.y + xv.z * q4.z + xv.w * q4.w;
        float ks = xv.x * k4.x + xv.y * k4.y + xv.z * k4.z + xv.w * k4.w;
#pragma unroll
        for (int o = 16; o; o >>= 1) {
            qs += __shfl_xor_sync(0xffffffffu, qs, o);
            ks += __shfl_xor_sync(0xffffffffu, ks, o);
        }
        if (lane == 0) { g_qx[n * Rr + r] = qs; g_kx[n * Rr + r] = ks; }
    }
}

// ---------------- fused edge kernel: warp per dst, online softmax, no atomics ----------------
#define ACASE(rr) case rr: acc[rr][0] = fmaf(wt, xv.x, acc[rr][0]); \
                           acc[rr][1] = fmaf(wt, xv.y, acc[rr][1]); \
                           acc[rr][2] = fmaf(wt, xv.z, acc[rr][2]); \
                           acc[rr][3] = fmaf(wt, xv.w, acc[rr][3]); break;

__global__ __launch_bounds__(256) void edge_kernel(const float* __restrict__ xin) {
    int gw = blockIdx.x * 8 + (threadIdx.x >> 5);
    int lane = threadIdx.x & 31;
    int d = gw;
    int beg = g_rowptr[d], end = g_rowptr[d + 1];
    float m = -1e30f, s = 0.f;
    float acc[Rr][4] = {};

    for (int j0 = beg; j0 < end; j0 += 32) {
        int j = j0 + lane;
        bool valid = j < end;
        int src = 0, et = 0;
        float a = -1e30f;
        if (valid) {
            src = g_esrc[j];
            et  = g_eet[j];
            a = g_qx[d * Rr + et] + g_kx[src * Rr + et];
            a = (a >= 0.f) ? a : 0.2f * a;
        }
        // group max
        float gm = a;
#pragma unroll
        for (int o = 16; o; o >>= 1) gm = fmaxf(gm, __shfl_xor_sync(0xffffffffu, gm, o));
        if (gm > m) {
            float sc = __expf(m - gm);
            s *= sc;
#pragma unroll
            for (int r = 0; r < Rr; r++) {
                acc[r][0] *= sc; acc[r][1] *= sc; acc[r][2] *= sc; acc[r][3] *= sc;
            }
            m = gm;
        }
        float w = valid ? __expf(a - m) : 0.f;
        float ws = w;
#pragma unroll
        for (int o = 16; o; o >>= 1) ws += __shfl_xor_sync(0xffffffffu, ws, o);
        s += ws;

        int cnt = min(32, end - j0);
        for (int t = 0; t < cnt; t++) {
            int   srct = __shfl_sync(0xffffffffu, src, t);
            int   ett  = __shfl_sync(0xffffffffu, et, t);
            float wt   = __shfl_sync(0xffffffffu, w, t);
            float4 xv = *(const float4*)&xin[(size_t)srct * Fd + lane * 4];
            switch (ett) {
                ACASE(0) ACASE(1) ACASE(2) ACASE(3)
                ACASE(4) ACASE(5) ACASE(6) ACASE(7)
            }
        }
    }
    float inv = (end > beg) ? (1.f / s) : 0.f;
#pragma unroll
    for (int r = 0; r < Rr; r++) {
        float4 o = make_float4(acc[r][0] * inv, acc[r][1] * inv,
                               acc[r][2] * inv, acc[r][3] * inv);
        *(float4*)&g_agg[(size_t)d * RH + r * Hd + lane * 4] = o;
    }
}

// ---------------- mma.sync bf16 3-pass GEMM: h = relu(agg[N,1024] @ Wcat^T + b) ----------------
#define KC 64
#define NKC (RH / KC)                 // 16
#define SSTR 72
#define BUF_BYTES (128 * SSTR * 2)    // 18432
#define OFF_AH 0
#define OFF_AL BUF_BYTES
#define OFF_BH (2 * BUF_BYTES)
#define OFF_BL (3 * BUF_BYTES)
#define SM_TOTAL (4 * BUF_BYTES)      // 73728

__global__ __launch_bounds__(256) void gemm_mma_kernel(const float* __restrict__ bias,
                                                       float* __restrict__ hout) {
    extern __shared__ __align__(16) char smem[];
    const int tid = threadIdx.x, wid = tid >> 5, lane = tid & 31;
    const int row0 = blockIdx.x * 128;
    const int wr = wid >> 2, wc = wid & 3;    // warp tile: rows 64*wr, cols 32*wc
    const uint32_t sb = smem_u32(smem);

    float acc[4][4][4] = {};

    for (int kc = 0; kc < NKC; kc++) {
        if (kc) __syncthreads();
        const int kbase = kc * KC;
        // A chunk: 128 rows x 64 k fp32 -> bf16 hi/lo
#pragma unroll
        for (int i = 0; i < 8; i++) {
            int cid = tid + i * 256;
            int row = cid >> 4;
            int c4  = (cid & 15) * 4;
            float4 v = make_float4(0.f, 0.f, 0.f, 0.f);
            int gr = row0 + row;
            if (gr < Nn) v = *(const float4*)&g_agg[(size_t)gr * RH + kbase + c4];
            __nv_bfloat16 h0 = __float2bfloat16(v.x), h1 = __float2bfloat16(v.y);
            __nv_bfloat16 h2 = __float2bfloat16(v.z), h3 = __float2bfloat16(v.w);
            __nv_bfloat16 l0 = __float2bfloat16(v.x - __bfloat162float(h0));
            __nv_bfloat16 l1 = __float2bfloat16(v.y - __bfloat162float(h1));
            __nv_bfloat16 l2 = __float2bfloat16(v.z - __bfloat162float(h2));
            __nv_bfloat16 l3 = __float2bfloat16(v.w - __bfloat162float(h3));
            __nv_bfloat162 ph0, ph1, pl0, pl1;
            ph0.x = h0; ph0.y = h1; ph1.x = h2; ph1.y = h3;
            pl0.x = l0; pl0.y = l1; pl1.x = l2; pl1.y = l3;
            uint2 sh, sl;
            sh.x = *(uint32_t*)&ph0; sh.y = *(uint32_t*)&ph1;
            sl.x = *(uint32_t*)&pl0; sl.y = *(uint32_t*)&pl1;
            uint32_t off = (uint32_t)(row * SSTR + c4) * 2;
            *(uint2*)(smem + OFF_AH + off) = sh;
            *(uint2*)(smem + OFF_AL + off) = sl;
        }
        // B chunk: 128 rows (h) x 64 k bf16 hi/lo
#pragma unroll
        for (int i = 0; i < 4; i++) {
            int cid = tid + i * 256;
            int row = cid >> 3;
            int k0  = (cid & 7) * 8;
            size_t gidx = (size_t)row * RH + kbase + k0;
            uint4 vh = *(const uint4*)&g_Wbh[gidx];
            uint4 vl = *(const uint4*)&g_Wbl[gidx];
            uint32_t off = (uint32_t)(row * SSTR + k0) * 2;
            *(uint4*)(smem + OFF_BH + off) = vh;
            *(uint4*)(smem + OFF_BL + off) = vl;
        }
        __syncthreads();

#pragma unroll
        for (int ks = 0; ks < 4; ks++) {
            const int k0 = ks * 16;
            const uint32_t lrow = lane & 15;
            const uint32_t lcol = (k0 + ((lane >> 4) << 3)) * 2;
            uint32_t ah[4][4], al[4][4], bh[2][4], bl[2][4];
#pragma unroll
            for (int mt = 0; mt < 4; mt++) {
                uint32_t base = sb + (wr * 64 + mt * 16 + lrow) * (SSTR * 2) + lcol;
                ldsm_x4(ah[mt], base + OFF_AH);
                ldsm_x4(al[mt], base + OFF_AL);
            }
#pragma unroll
            for (int p = 0; p < 2; p++) {
                uint32_t base = sb + (wc * 32 + p * 16 + lrow) * (SSTR * 2) + lcol;
                ldsm_x4(bh[p], base + OFF_BH);
                ldsm_x4(bl[p], base + OFF_BL);
            }
#pragma unroll
            for (int mt = 0; mt < 4; mt++)
#pragma unroll
                for (int p = 0; p < 2; p++)
#pragma unroll
                    for (int q = 0; q < 2; q++) {
                        float* c = acc[mt][p * 2 + q];
                        mma_bf16(c, ah[mt], bh[p][q], bh[p][q + 2]);
                        mma_bf16(c, ah[mt], bl[p][q], bl[p][q + 2]);
                        mma_bf16(c, al[mt], bh[p][q], bh[p][q + 2]);
                    }
        }
    }
    __syncthreads();

    // stage accumulators -> smem
    float (*stage)[132] = (float(*)[132])smem;
#pragma unroll
    for (int mt = 0; mt < 4; mt++)
#pragma unroll
        for (int nt = 0; nt < 4; nt++) {
            int rr = wr * 64 + mt * 16 + (lane >> 2);
            int cc = wc * 32 + nt * 8 + (lane & 3) * 2;
            stage[rr][cc]     = acc[mt][nt][0];
            stage[rr][cc + 1] = acc[mt][nt][1];
            stage[rr + 8][cc]     = acc[mt][nt][2];
            stage[rr + 8][cc + 1] = acc[mt][nt][3];
        }
    __syncthreads();

    // bias + relu + coalesced store
#pragma unroll
    for (int i = 0; i < 16; i++) {
        int cid = tid + i * 256;
        int row = cid >> 5;
        int c4  = (cid & 31) * 4;
        int node = row0 + row;
        if (node < Nn) {
            float4 v = *(const float4*)&stage[row][c4];
            v.x = fmaxf(v.x + __ldg(&bias[c4]),     0.f);
            v.y = fmaxf(v.y + __ldg(&bias[c4 + 1]), 0.f);
            v.z = fmaxf(v.z + __ldg(&bias[c4 + 2]), 0.f);
            v.w = fmaxf(v.w + __ldg(&bias[c4 + 3]), 0.f);
            *(float4*)&hout[(size_t)node * Hd + c4] = v;
        }
    }
}

// ---------------- final linear + log_softmax ----------------
__global__ __launch_bounds__(256) void final_kernel(const float* __restrict__ h,
                                                    const float* __restrict__ lw,
                                                    const float* __restrict__ lb,
                                                    float* __restrict__ out) {
    __shared__ float sh[8][Hd];
    int tid = threadIdx.x;
    int nodeBase = blockIdx.x * 8;
#pragma unroll
    for (int l = 0; l < 4; l++) {
        int idx = tid + l * 256;
        sh[idx >> 7][idx & 127] = h[(size_t)nodeBase * Hd + idx];
    }
    __syncthreads();
    int w = tid >> 5, lane = tid & 31;
    int n = nodeBase + w;
    float a0 = lb[lane], a1 = lb[lane + 32];
#pragma unroll 16
    for (int f = 0; f < Hd; f++) {
        float hv = sh[w][f];
        a0 = fmaf(hv, lw[f * Cc + lane], a0);
        a1 = fmaf(hv, lw[f * Cc + lane + 32], a1);
    }
    float mx = fmaxf(a0, a1);
#pragma unroll
    for (int o = 16; o; o >>= 1) mx = fmaxf(mx, __shfl_xor_sync(0xffffffffu, mx, o));
    float s = expf(a0 - mx) + expf(a1 - mx);
#pragma unroll
    for (int o = 16; o; o >>= 1) s += __shfl_xor_sync(0xffffffffu, s, o);
    float lse = mx + logf(s);
    out[(size_t)n * Cc + lane]      = a0 - lse;
    out[(size_t)n * Cc + lane + 32] = a1 - lse;
}

// ---------------- host orchestration ----------------
static void run_layer(const float* xin, const float* W, const float* q,
                      const float* k, const float* b, float* hout) {
    wqk_kernel<<<(Rr * Fd * 32 + 255) / 256, 256>>>(W, q, k);
    wprep_kernel<<<(Hd * RH + 255) / 256, 256>>>(W);
    qxkx_kernel<<<Nn / 8, 256>>>(xin);
    edge_kernel<<<Nn / 8, 256>>>(xin);
    gemm_mma_kernel<<<(Nn + 127) / 128, 256, SM_TOTAL>>>(b, hout);
}

extern "C" void kernel_launch(void* const* d_in, const int* in_sizes, int n_in,
                              void* d_out, int out_size) {
    const float* x     = (const float*)d_in[0];
    const void*  ei    = d_in[1];
    const void*  et    = d_in[2];
    const float* W1    = (const float*)d_in[3];
    const float* q1    = (const float*)d_in[4];
    const float* k1    = (const float*)d_in[5];
    const float* b1    = (const float*)d_in[6];
    const float* W2    = (const float*)d_in[7];
    const float* q2    = (const float*)d_in[8];
    const float* k2    = (const float*)d_in[9];
    const float* b2    = (const float*)d_in[10];
    const float* W3    = (const float*)d_in[11];
    const float* q3    = (const float*)d_in[12];
    const float* k3    = (const float*)d_in[13];
    const float* b3    = (const float*)d_in[14];
    const float* lin_w = (const float*)d_in[15];
    const float* lin_b = (const float*)d_in[16];

    cudaFuncSetAttribute(gemm_mma_kernel,
                         cudaFuncAttributeMaxDynamicSharedMemorySize, SM_TOTAL);

    float *hA = nullptr, *hB = nullptr;
    cudaGetSymbolAddress((void**)&hA, g_hA);
    cudaGetSymbolAddress((void**)&hB, g_hB);

    detect_kernel<<<1, 32>>>((const unsigned*)ei);
    convert_kernel<<<(Ee + 255) / 256, 256>>>(ei, et);

    // CSR build (once per launch)
    zero_kernel<<<(Nn + 255) / 256, 256>>>();
    hist_kernel<<<(Ee + 255) / 256, 256>>>();
    scan1_kernel<<<NB, SCANB>>>();
    scan2_kernel<<<1, 32>>>();
    scan3_kernel<<<(Nn + 255) / 256, 256>>>();
    scatter_kernel<<<(Ee + 255) / 256, 256>>>();

    run_layer(x,  W1, q1, k1, b1, hA);
    run_layer(hA, W2, q2, k2, b2, hB);
    run_layer(hB, W3, q3, k3, b3, hA);

    final_kernel<<<Nn / 8, 256>>>(hA, lin_w, lin_b, (float*)d_out);
}

// round 5
// speedup vs baseline: 1.3056x; 1.3056x over previous
#include <cuda_runtime.h>
#include <cuda_bf16.h>
#include <cstdint>

#define Nn 50000
#define Ee 800000
#define Rr 8
#define Fd 128
#define Hd 128
#define Cc 64
#define RH (Rr * Hd)   // 1024
#define SCANB 512
#define NB ((Nn + SCANB - 1) / SCANB)   // 98

// ---------------- device scratch ----------------
__device__ float         g_agg[(size_t)Nn * RH];   // aggregated features [N, R*F]
__device__ float         g_hA[Nn * Hd];
__device__ float         g_hB[Nn * Hd];
__device__ float         g_qx[Nn * Rr];
__device__ float         g_kx[Nn * Rr];
__device__ __nv_bfloat16 g_Wbh[Hd * RH];   // Wcat [h][r*128+f] hi
__device__ __nv_bfloat16 g_Wbl[Hd * RH];   // lo
__device__ float         g_Wq[Rr * Fd];
__device__ float         g_Wk[Rr * Fd];
__device__ int           g_src[Ee];
__device__ int           g_dst[Ee];
__device__ int           g_et[Ee];
__device__ int           g_esrc[Ee];       // CSR-sorted by dst
__device__ int           g_eet[Ee];
__device__ int           g_rowptr[Nn + 1];
__device__ int           g_rpp[Nn];
__device__ int           g_bsum[NB + 1];
__device__ int           g_cnt[Nn];
__device__ int           g_fill[Nn];
__device__ int           g_is64;

// ---------------- helpers ----------------
__device__ __forceinline__ uint32_t smem_u32(const void* p) {
    uint32_t a;
    asm("{ .reg .u64 t; cvta.to.shared.u64 t, %1; cvt.u32.u64 %0, t; }" : "=r"(a) : "l"(p));
    return a;
}
__device__ __forceinline__ void ldsm_x4(uint32_t* r, uint32_t addr) {
    asm volatile("ldmatrix.sync.aligned.m8n8.x4.shared.b16 {%0,%1,%2,%3}, [%4];"
                 : "=r"(r[0]), "=r"(r[1]), "=r"(r[2]), "=r"(r[3]) : "r"(addr));
}
__device__ __forceinline__ void mma_bf16(float* c, const uint32_t* a, uint32_t b0, uint32_t b1) {
    asm volatile(
        "mma.sync.aligned.m16n8k16.row.col.f32.bf16.bf16.f32 "
        "{%0,%1,%2,%3}, {%4,%5,%6,%7}, {%8,%9}, {%0,%1,%2,%3};"
        : "+f"(c[0]), "+f"(c[1]), "+f"(c[2]), "+f"(c[3])
        : "r"(a[0]), "r"(a[1]), "r"(a[2]), "r"(a[3]), "r"(b0), "r"(b1));
}

// ---------------- dtype detect + edge conversion ----------------
__global__ void detect_kernel(const unsigned* __restrict__ ei) {
    if (threadIdx.x == 0 && blockIdx.x == 0) {
        int zeros = 0;
        for (int i = 0; i < 128; i++)
            if (ei[2 * i + 1] == 0u) zeros++;
        g_is64 = (zeros == 128) ? 1 : 0;
    }
}

__global__ void convert_kernel(const void* __restrict__ ei, const void* __restrict__ et) {
    int e = blockIdx.x * blockDim.x + threadIdx.x;
    if (e >= Ee) return;
    if (g_is64) {
        const long long* p = (const long long*)ei;
        g_src[e] = (int)p[e];
        g_dst[e] = (int)p[Ee + e];
        g_et[e]  = (int)((const long long*)et)[e];
    } else {
        const int* p = (const int*)ei;
        g_src[e] = p[e];
        g_dst[e] = p[Ee + e];
        g_et[e]  = ((const int*)et)[e];
    }
}

// ---------------- CSR build (once; graph shared across layers) ----------------
__global__ void zero_kernel() {
    int i = blockIdx.x * blockDim.x + threadIdx.x;
    if (i < Nn) { g_cnt[i] = 0; g_fill[i] = 0; }
}
__global__ void hist_kernel() {
    int e = blockIdx.x * blockDim.x + threadIdx.x;
    if (e < Ee) atomicAdd(&g_cnt[g_dst[e]], 1);
}
__global__ void scan1_kernel() {
    __shared__ int ss[SCANB];
    int t = threadIdx.x;
    int idx = blockIdx.x * SCANB + t;
    int v = (idx < Nn) ? g_cnt[idx] : 0;
    ss[t] = v;
    __syncthreads();
    for (int off = 1; off < SCANB; off <<= 1) {
        int tmp = (t >= off) ? ss[t - off] : 0;
        __syncthreads();
        ss[t] += tmp;
        __syncthreads();
    }
    if (idx < Nn) g_rpp[idx] = ss[t] - v;       // exclusive within block
    if (t == SCANB - 1) g_bsum[blockIdx.x] = ss[t];
}
__global__ void scan2_kernel() {
    if (threadIdx.x == 0 && blockIdx.x == 0) {
        int total = 0;
        for (int b = 0; b < NB; b++) { int v = g_bsum[b]; g_bsum[b] = total; total += v; }
        g_rowptr[Nn] = total;
    }
}
__global__ void scan3_kernel() {
    int idx = blockIdx.x * blockDim.x + threadIdx.x;
    if (idx < Nn) g_rowptr[idx] = g_rpp[idx] + g_bsum[idx >> 9];
}
__global__ void scatter_kernel() {
    int e = blockIdx.x * blockDim.x + threadIdx.x;
    if (e >= Ee) return;
    int d = g_dst[e];
    int p = g_rowptr[d] + atomicAdd(&g_fill[d], 1);
    g_esrc[p] = g_src[e];
    g_eet[p]  = g_et[e];
}

// ---------------- weight prep ----------------
__global__ void wqk_kernel(const float* __restrict__ W,
                           const float* __restrict__ q,
                           const float* __restrict__ k) {
    int warp = (blockIdx.x * blockDim.x + threadIdx.x) >> 5;
    int lane = threadIdx.x & 31;
    if (warp >= Rr * Fd) return;
    const float* wrow = W + (size_t)warp * Hd;
    float sq = 0.f, sk = 0.f;
#pragma unroll
    for (int j = 0; j < 4; j++) {
        float wv = wrow[lane + 32 * j];
        sq += wv * q[lane + 32 * j];
        sk += wv * k[lane + 32 * j];
    }
#pragma unroll
    for (int o = 16; o; o >>= 1) {
        sq += __shfl_xor_sync(0xffffffffu, sq, o);
        sk += __shfl_xor_sync(0xffffffffu, sk, o);
    }
    if (lane == 0) { g_Wq[warp] = sq; g_Wk[warp] = sk; }
}

__global__ void wprep_kernel(const float* __restrict__ W) {
    int idx = blockIdx.x * blockDim.x + threadIdx.x;   // over Hd*RH
    if (idx >= Hd * RH) return;
    int kk = idx & (RH - 1);
    int h  = idx >> 10;
    int f  = kk & 127;
    int r  = kk >> 7;
    float v = W[(size_t)r * Fd * Hd + (size_t)f * Hd + h];
    __nv_bfloat16 hi = __float2bfloat16(v);
    __nv_bfloat16 lo = __float2bfloat16(v - __bfloat162float(hi));
    g_Wbh[idx] = hi;
    g_Wbl[idx] = lo;
}

// ---------------- qx/kx: warp per node ----------------
__global__ __launch_bounds__(256) void qxkx_kernel(const float* __restrict__ xin) {
    __shared__ float sq[Rr][Fd], sk[Rr][Fd];
    int tid = threadIdx.x;
    for (int i = tid; i < Rr * Fd; i += 256) {
        sq[i >> 7][i & 127] = g_Wq[i];
        sk[i >> 7][i & 127] = g_Wk[i];
    }
    __syncthreads();
    int w = tid >> 5, lane = tid & 31;
    int n = blockIdx.x * 8 + w;
    float4 xv = *(const float4*)&xin[(size_t)n * Fd + lane * 4];
#pragma unroll
    for (int r = 0; r < Rr; r++) {
        float4 q4 = *(const float4*)&sq[r][lane * 4];
        float4 k4 = *(const float4*)&sk[r][lane * 4];
        float qs = xv.x * q4.x + xv.y * q4.y + xv.z * q4.z + xv.w * q4.w;
        float ks = xv.x * k4.x + xv.y * k4.y + xv.z * k4.z + xv.w * k4.w;
#pragma unroll
        for (int o = 16; o; o >>= 1) {
            qs += __shfl_xor_sync(0xffffffffu, qs, o);
            ks += __shfl_xor_sync(0xffffffffu, ks, o);
        }
        if (lane == 0) { g_qx[n * Rr + r] = qs; g_kx[n * Rr + r] = ks; }
    }
}

// ---------------- fused edge kernel: BLOCK(128) per dst, feature-parallel ----------------
#define ECASE(rr) case rr: acc##rr = fmaf(wt, xv, acc##rr); break;

__global__ __launch_bounds__(128) void edge_kernel(const float* __restrict__ xin) {
    const int d = blockIdx.x;
    const int tid = threadIdx.x, wid = tid >> 5, lane = tid & 31;
    __shared__ float sw[128];
    __shared__ int   ssrc[128];
    __shared__ int   sett[128];
    __shared__ float red[4];

    const int beg = g_rowptr[d], end = g_rowptr[d + 1];
    float acc0 = 0.f, acc1 = 0.f, acc2 = 0.f, acc3 = 0.f;
    float acc4 = 0.f, acc5 = 0.f, acc6 = 0.f, acc7 = 0.f;
    float m = -1e30f, s = 0.f;

    for (int j0 = beg; j0 < end; j0 += 128) {
        const int cnt = min(128, end - j0);
        float a = -1e30f;
        int src = 0, et = 0;
        if (tid < cnt) {
            src = g_esrc[j0 + tid];
            et  = g_eet[j0 + tid];
            a = g_qx[d * Rr + et] + g_kx[src * Rr + et];
            a = (a >= 0.f) ? a : 0.2f * a;
        }
        ssrc[tid] = src;
        sett[tid] = et;
        // block max
        float gm = a;
#pragma unroll
        for (int o = 16; o; o >>= 1) gm = fmaxf(gm, __shfl_xor_sync(0xffffffffu, gm, o));
        if (lane == 0) red[wid] = gm;
        __syncthreads();
        gm = fmaxf(fmaxf(red[0], red[1]), fmaxf(red[2], red[3]));
        if (gm > m) {
            float sc = __expf(m - gm);
            s *= sc;
            acc0 *= sc; acc1 *= sc; acc2 *= sc; acc3 *= sc;
            acc4 *= sc; acc5 *= sc; acc6 *= sc; acc7 *= sc;
            m = gm;
        }
        float w = (tid < cnt) ? __expf(a - m) : 0.f;
        sw[tid] = w;
        float ws = w;
#pragma unroll
        for (int o = 16; o; o >>= 1) ws += __shfl_xor_sync(0xffffffffu, ws, o);
        __syncthreads();           // red[] max reads done
        if (lane == 0) red[wid] = ws;
        __syncthreads();
        s += red[0] + red[1] + red[2] + red[3];

        // feature-parallel accumulate: one coalesced row load + one fma per edge
        for (int t = 0; t < cnt; t++) {
            float wt  = sw[t];
            int srct  = ssrc[t];
            int ett   = sett[t];
            float xv = __ldg(&xin[(size_t)srct * Fd + tid]);
            switch (ett) {
                ECASE(0) ECASE(1) ECASE(2) ECASE(3)
                ECASE(4) ECASE(5) ECASE(6) ECASE(7)
            }
        }
        __syncthreads();           // before next chunk overwrites smem
    }

    float inv = (end > beg) ? (1.f / s) : 0.f;
    float* o = &g_agg[(size_t)d * RH + tid];
    o[0 * Hd] = acc0 * inv; o[1 * Hd] = acc1 * inv;
    o[2 * Hd] = acc2 * inv; o[3 * Hd] = acc3 * inv;
    o[4 * Hd] = acc4 * inv; o[5 * Hd] = acc5 * inv;
    o[6 * Hd] = acc6 * inv; o[7 * Hd] = acc7 * inv;
}

// ---------------- mma.sync bf16 3-pass GEMM: h = relu(agg[N,1024] @ Wcat^T + b) ----------------
#define KC 64
#define NKC (RH / KC)                 // 16
#define SSTR 72
#define BUF_BYTES (128 * SSTR * 2)    // 18432
#define OFF_AH 0
#define OFF_AL BUF_BYTES
#define OFF_BH (2 * BUF_BYTES)
#define OFF_BL (3 * BUF_BYTES)
#define SM_TOTAL (4 * BUF_BYTES)      // 73728

__global__ __launch_bounds__(256) void gemm_mma_kernel(const float* __restrict__ bias,
                                                       float* __restrict__ hout) {
    extern __shared__ __align__(16) char smem[];
    const int tid = threadIdx.x, wid = tid >> 5, lane = tid & 31;
    const int row0 = blockIdx.x * 128;
    const int wr = wid >> 2, wc = wid & 3;
    const uint32_t sb = smem_u32(smem);

    float acc[4][4][4] = {};

    for (int kc = 0; kc < NKC; kc++) {
        if (kc) __syncthreads();
        const int kbase = kc * KC;
#pragma unroll
        for (int i = 0; i < 8; i++) {
            int cid = tid + i * 256;
            int row = cid >> 4;
            int c4  = (cid & 15) * 4;
            float4 v = make_float4(0.f, 0.f, 0.f, 0.f);
            int gr = row0 + row;
            if (gr < Nn) v = *(const float4*)&g_agg[(size_t)gr * RH + kbase + c4];
            __nv_bfloat16 h0 = __float2bfloat16(v.x), h1 = __float2bfloat16(v.y);
            __nv_bfloat16 h2 = __float2bfloat16(v.z), h3 = __float2bfloat16(v.w);
            __nv_bfloat16 l0 = __float2bfloat16(v.x - __bfloat162float(h0));
            __nv_bfloat16 l1 = __float2bfloat16(v.y - __bfloat162float(h1));
            __nv_bfloat16 l2 = __float2bfloat16(v.z - __bfloat162float(h2));
            __nv_bfloat16 l3 = __float2bfloat16(v.w - __bfloat162float(h3));
            __nv_bfloat162 ph0, ph1, pl0, pl1;
            ph0.x = h0; ph0.y = h1; ph1.x = h2; ph1.y = h3;
            pl0.x = l0; pl0.y = l1; pl1.x = l2; pl1.y = l3;
            uint2 sh, sl;
            sh.x = *(uint32_t*)&ph0; sh.y = *(uint32_t*)&ph1;
            sl.x = *(uint32_t*)&pl0; sl.y = *(uint32_t*)&pl1;
            uint32_t off = (uint32_t)(row * SSTR + c4) * 2;
            *(uint2*)(smem + OFF_AH + off) = sh;
            *(uint2*)(smem + OFF_AL + off) = sl;
        }
#pragma unroll
        for (int i = 0; i < 4; i++) {
            int cid = tid + i * 256;
            int row = cid >> 3;
            int k0  = (cid & 7) * 8;
            size_t gidx = (size_t)row * RH + kbase + k0;
            uint4 vh = *(const uint4*)&g_Wbh[gidx];
            uint4 vl = *(const uint4*)&g_Wbl[gidx];
            uint32_t off = (uint32_t)(row * SSTR + k0) * 2;
            *(uint4*)(smem + OFF_BH + off) = vh;
            *(uint4*)(smem + OFF_BL + off) = vl;
        }
        __syncthreads();

#pragma unroll
        for (int ks = 0; ks < 4; ks++) {
            const int k0 = ks * 16;
            const uint32_t lrow = lane & 15;
            const uint32_t lcol = (k0 + ((lane >> 4) << 3)) * 2;
            uint32_t ah[4][4], al[4][4], bh[2][4], bl[2][4];
#pragma unroll
            for (int mt = 0; mt < 4; mt++) {
                uint32_t base = sb + (wr * 64 + mt * 16 + lrow) * (SSTR * 2) + lcol;
                ldsm_x4(ah[mt], base + OFF_AH);
                ldsm_x4(al[mt], base + OFF_AL);
            }
#pragma unroll
            for (int p = 0; p < 2; p++) {
                uint32_t base = sb + (wc * 32 + p * 16 + lrow) * (SSTR * 2) + lcol;
                ldsm_x4(bh[p], base + OFF_BH);
                ldsm_x4(bl[p], base + OFF_BL);
            }
#pragma unroll
            for (int mt = 0; mt < 4; mt++)
#pragma unroll
                for (int p = 0; p < 2; p++)
#pragma unroll
                    for (int q = 0; q < 2; q++) {
                        float* c = acc[mt][p * 2 + q];
                        mma_bf16(c, ah[mt], bh[p][q], bh[p][q + 2]);
                        mma_bf16(c, ah[mt], bl[p][q], bl[p][q + 2]);
                        mma_bf16(c, al[mt], bh[p][q], bh[p][q + 2]);
                    }
        }
    }
    __syncthreads();

    float (*stage)[132] = (float(*)[132])smem;
#pragma unroll
    for (int mt = 0; mt < 4; mt++)
#pragma unroll
        for (int nt = 0; nt < 4; nt++) {
            int rr = wr * 64 + mt * 16 + (lane >> 2);
            int cc = wc * 32 + nt * 8 + (lane & 3) * 2;
            stage[rr][cc]     = acc[mt][nt][0];
            stage[rr][cc + 1] = acc[mt][nt][1];
            stage[rr + 8][cc]     = acc[mt][nt][2];
            stage[rr + 8][cc + 1] = acc[mt][nt][3];
        }
    __syncthreads();

#pragma unroll
    for (int i = 0; i < 16; i++) {
        int cid = tid + i * 256;
        int row = cid >> 5;
        int c4  = (cid & 31) * 4;
        int node = row0 + row;
        if (node < Nn) {
            float4 v = *(const float4*)&stage[row][c4];
            v.x = fmaxf(v.x + __ldg(&bias[c4]),     0.f);
            v.y = fmaxf(v.y + __ldg(&bias[c4 + 1]), 0.f);
            v.z = fmaxf(v.z + __ldg(&bias[c4 + 2]), 0.f);
            v.w = fmaxf(v.w + __ldg(&bias[c4 + 3]), 0.f);
            *(float4*)&hout[(size_t)node * Hd + c4] = v;
        }
    }
}

// ---------------- final linear + log_softmax ----------------
__global__ __launch_bounds__(256) void final_kernel(const float* __restrict__ h,
                                                    const float* __restrict__ lw,
                                                    const float* __restrict__ lb,
                                                    float* __restrict__ out) {
    __shared__ float sh[8][Hd];
    int tid = threadIdx.x;
    int nodeBase = blockIdx.x * 8;
#pragma unroll
    for (int l = 0; l < 4; l++) {
        int idx = tid + l * 256;
        sh[idx >> 7][idx & 127] = h[(size_t)nodeBase * Hd + idx];
    }
    __syncthreads();
    int w = tid >> 5, lane = tid & 31;
    int n = nodeBase + w;
    float a0 = lb[lane], a1 = lb[lane + 32];
#pragma unroll 16
    for (int f = 0; f < Hd; f++) {
        float hv = sh[w][f];
        a0 = fmaf(hv, lw[f * Cc + lane], a0);
        a1 = fmaf(hv, lw[f * Cc + lane + 32], a1);
    }
    float mx = fmaxf(a0, a1);
#pragma unroll
    for (int o = 16; o; o >>= 1) mx = fmaxf(mx, __shfl_xor_sync(0xffffffffu, mx, o));
    float s = expf(a0 - mx) + expf(a1 - mx);
#pragma unroll
    for (int o = 16; o; o >>= 1) s += __shfl_xor_sync(0xffffffffu, s, o);
    float lse = mx + logf(s);
    out[(size_t)n * Cc + lane]      = a0 - lse;
    out[(size_t)n * Cc + lane + 32] = a1 - lse;
}

// ---------------- host orchestration ----------------
static void run_layer(const float* xin, const float* W, const float* q,
                      const float* k, const float* b, float* hout) {
    wqk_kernel<<<(Rr * Fd * 32 + 255) / 256, 256>>>(W, q, k);
    wprep_kernel<<<(Hd * RH + 255) / 256, 256>>>(W);
    qxkx_kernel<<<Nn / 8, 256>>>(xin);
    edge_kernel<<<Nn, 128>>>(xin);
    gemm_mma_kernel<<<(Nn + 127) / 128, 256, SM_TOTAL>>>(b, hout);
}

extern "C" void kernel_launch(void* const* d_in, const int* in_sizes, int n_in,
                              void* d_out, int out_size) {
    const float* x     = (const float*)d_in[0];
    const void*  ei    = d_in[1];
    const void*  et    = d_in[2];
    const float* W1    = (const float*)d_in[3];
    const float* q1    = (const float*)d_in[4];
    const float* k1    = (const float*)d_in[5];
    const float* b1    = (const float*)d_in[6];
    const float* W2    = (const float*)d_in[7];
    const float* q2    = (const float*)d_in[8];
    const float* k2    = (const float*)d_in[9];
    const float* b2    = (const float*)d_in[10];
    const float* W3    = (const float*)d_in[11];
    const float* q3    = (const float*)d_in[12];
    const float* k3    = (const float*)d_in[13];
    const float* b3    = (const float*)d_in[14];
    const float* lin_w = (const float*)d_in[15];
    const float* lin_b = (const float*)d_in[16];

    cudaFuncSetAttribute(gemm_mma_kernel,
                         cudaFuncAttributeMaxDynamicSharedMemorySize, SM_TOTAL);

    float *hA = nullptr, *hB = nullptr;
    cudaGetSymbolAddress((void**)&hA, g_hA);
    cudaGetSymbolAddress((void**)&hB, g_hB);

    detect_kernel<<<1, 32>>>((const unsigned*)ei);
    convert_kernel<<<(Ee + 255) / 256, 256>>>(ei, et);

    // CSR build (once per launch)
    zero_kernel<<<(Nn + 255) / 256, 256>>>();
    hist_kernel<<<(Ee + 255) / 256, 256>>>();
    scan1_kernel<<<NB, SCANB>>>();
    scan2_kernel<<<1, 32>>>();
    scan3_kernel<<<(Nn + 255) / 256, 256>>>();
    scatter_kernel<<<(Ee + 255) / 256, 256>>>();

    run_layer(x,  W1, q1, k1, b1, hA);
    run_layer(hA, W2, q2, k2, b2, hB);
    run_layer(hB, W3, q3, k3, b3, hA);

    final_kernel<<<Nn / 8, 256>>>(hA, lin_w, lin_b, (float*)d_out);
}

// round 6
// speedup vs baseline: 1.3312x; 1.0196x over previous
#include <cuda_runtime.h>
#include <cuda_bf16.h>
#include <cstdint>

#define Nn 50000
#define Ee 800000
#define Rr 8
#define Fd 128
#define Hd 128
#define Cc 64
#define RH (Rr * Hd)   // 1024
#define SCANB 512
#define NB ((Nn + SCANB - 1) / SCANB)   // 98

// ---------------- device scratch ----------------
__device__ __nv_bfloat16 g_aggH[(size_t)Nn * RH];  // aggregated features hi
__device__ __nv_bfloat16 g_aggL[(size_t)Nn * RH];  // lo
__device__ float         g_hA[Nn * Hd];
__device__ float         g_hB[Nn * Hd];
__device__ float         g_qx[Nn * Rr];
__device__ float         g_kx[Nn * Rr];
__device__ __nv_bfloat16 g_Wbh[Hd * RH];   // Wcat [h][r*128+f] hi
__device__ __nv_bfloat16 g_Wbl[Hd * RH];   // lo
__device__ float         g_Wq[Rr * Fd];
__device__ float         g_Wk[Rr * Fd];
__device__ int           g_src[Ee];
__device__ int           g_dst[Ee];
__device__ int           g_et[Ee];
__device__ int           g_esrc[Ee];       // CSR-sorted by dst
__device__ int           g_eet[Ee];
__device__ int           g_rowptr[Nn + 1];
__device__ int           g_rpp[Nn];
__device__ int           g_bsum[NB + 1];
__device__ int           g_cnt[Nn];
__device__ int           g_fill[Nn];
__device__ int           g_is64;

// ---------------- helpers ----------------
__device__ __forceinline__ uint32_t smem_u32(const void* p) {
    uint32_t a;
    asm("{ .reg .u64 t; cvta.to.shared.u64 t, %1; cvt.u32.u64 %0, t; }" : "=r"(a) : "l"(p));
    return a;
}
__device__ __forceinline__ void ldsm_x4(uint32_t* r, uint32_t addr) {
    asm volatile("ldmatrix.sync.aligned.m8n8.x4.shared.b16 {%0,%1,%2,%3}, [%4];"
                 : "=r"(r[0]), "=r"(r[1]), "=r"(r[2]), "=r"(r[3]) : "r"(addr));
}
__device__ __forceinline__ void mma_bf16(float* c, const uint32_t* a, uint32_t b0, uint32_t b1) {
    asm volatile(
        "mma.sync.aligned.m16n8k16.row.col.f32.bf16.bf16.f32 "
        "{%0,%1,%2,%3}, {%4,%5,%6,%7}, {%8,%9}, {%0,%1,%2,%3};"
        : "+f"(c[0]), "+f"(c[1]), "+f"(c[2]), "+f"(c[3])
        : "r"(a[0]), "r"(a[1]), "r"(a[2]), "r"(a[3]), "r"(b0), "r"(b1));
}
__device__ __forceinline__ void cp16(uint32_t saddr, const void* g, int srcsize) {
    asm volatile("cp.async.cg.shared.global [%0], [%1], 16, %2;"
                 :: "r"(saddr), "l"(g), "r"(srcsize));
}

// ---------------- dtype detect + edge conversion ----------------
__global__ void detect_kernel(const unsigned* __restrict__ ei) {
    if (threadIdx.x == 0 && blockIdx.x == 0) {
        int zeros = 0;
        for (int i = 0; i < 128; i++)
            if (ei[2 * i + 1] == 0u) zeros++;
        g_is64 = (zeros == 128) ? 1 : 0;
    }
}

__global__ void convert_kernel(const void* __restrict__ ei, const void* __restrict__ et) {
    int e = blockIdx.x * blockDim.x + threadIdx.x;
    if (e >= Ee) return;
    if (g_is64) {
        const long long* p = (const long long*)ei;
        g_src[e] = (int)p[e];
        g_dst[e] = (int)p[Ee + e];
        g_et[e]  = (int)((const long long*)et)[e];
    } else {
        const int* p = (const int*)ei;
        g_src[e] = p[e];
        g_dst[e] = p[Ee + e];
        g_et[e]  = ((const int*)et)[e];
    }
}

// ---------------- CSR build (once; graph shared across layers) ----------------
__global__ void zero_kernel() {
    int i = blockIdx.x * blockDim.x + threadIdx.x;
    if (i < Nn) { g_cnt[i] = 0; g_fill[i] = 0; }
}
__global__ void hist_kernel() {
    int e = blockIdx.x * blockDim.x + threadIdx.x;
    if (e < Ee) atomicAdd(&g_cnt[g_dst[e]], 1);
}
__global__ void scan1_kernel() {
    __shared__ int ss[SCANB];
    int t = threadIdx.x;
    int idx = blockIdx.x * SCANB + t;
    int v = (idx < Nn) ? g_cnt[idx] : 0;
    ss[t] = v;
    __syncthreads();
    for (int off = 1; off < SCANB; off <<= 1) {
        int tmp = (t >= off) ? ss[t - off] : 0;
        __syncthreads();
        ss[t] += tmp;
        __syncthreads();
    }
    if (idx < Nn) g_rpp[idx] = ss[t] - v;
    if (t == SCANB - 1) g_bsum[blockIdx.x] = ss[t];
}
__global__ void scan2_kernel() {
    if (threadIdx.x == 0 && blockIdx.x == 0) {
        int total = 0;
        for (int b = 0; b < NB; b++) { int v = g_bsum[b]; g_bsum[b] = total; total += v; }
        g_rowptr[Nn] = total;
    }
}
__global__ void scan3_kernel() {
    int idx = blockIdx.x * blockDim.x + threadIdx.x;
    if (idx < Nn) g_rowptr[idx] = g_rpp[idx] + g_bsum[idx >> 9];
}
__global__ void scatter_kernel() {
    int e = blockIdx.x * blockDim.x + threadIdx.x;
    if (e >= Ee) return;
    int d = g_dst[e];
    int p = g_rowptr[d] + atomicAdd(&g_fill[d], 1);
    g_esrc[p] = g_src[e];
    g_eet[p]  = g_et[e];
}

// ---------------- weight prep ----------------
__global__ void wqk_kernel(const float* __restrict__ W,
                           const float* __restrict__ q,
                           const float* __restrict__ k) {
    int warp = (blockIdx.x * blockDim.x + threadIdx.x) >> 5;
    int lane = threadIdx.x & 31;
    if (warp >= Rr * Fd) return;
    const float* wrow = W + (size_t)warp * Hd;
    float sq = 0.f, sk = 0.f;
#pragma unroll
    for (int j = 0; j < 4; j++) {
        float wv = wrow[lane + 32 * j];
        sq += wv * q[lane + 32 * j];
        sk += wv * k[lane + 32 * j];
    }
#pragma unroll
    for (int o = 16; o; o >>= 1) {
        sq += __shfl_xor_sync(0xffffffffu, sq, o);
        sk += __shfl_xor_sync(0xffffffffu, sk, o);
    }
    if (lane == 0) { g_Wq[warp] = sq; g_Wk[warp] = sk; }
}

// tiled transpose: W[r,f,h] -> Wcat[h][r*128+f] bf16 hi/lo, fully coalesced
__global__ void wprep_kernel(const float* __restrict__ W) {
    __shared__ float t[32][33];
    int r = blockIdx.z, f0 = blockIdx.x * 32, h0 = blockIdx.y * 32;
    int tx = threadIdx.x, ty = threadIdx.y;   // 32 x 8
#pragma unroll
    for (int i = 0; i < 4; i++) {
        int f = f0 + ty + i * 8;
        t[ty + i * 8][tx] = W[(size_t)r * Fd * Hd + (size_t)f * Hd + h0 + tx];
    }
    __syncthreads();
#pragma unroll
    for (int i = 0; i < 4; i++) {
        int h = h0 + ty + i * 8;
        float v = t[tx][ty + i * 8];
        __nv_bfloat16 hi = __float2bfloat16(v);
        __nv_bfloat16 lo = __float2bfloat16(v - __bfloat162float(hi));
        size_t oidx = (size_t)h * RH + r * Hd + f0 + tx;
        g_Wbh[oidx] = hi;
        g_Wbl[oidx] = lo;
    }
}

// ---------------- qx/kx: warp per node ----------------
__global__ __launch_bounds__(256) void qxkx_kernel(const float* __restrict__ xin) {
    __shared__ float sq[Rr][Fd], sk[Rr][Fd];
    int tid = threadIdx.x;
    for (int i = tid; i < Rr * Fd; i += 256) {
        sq[i >> 7][i & 127] = g_Wq[i];
        sk[i >> 7][i & 127] = g_Wk[i];
    }
    __syncthreads();
    int w = tid >> 5, lane = tid & 31;
    int n = blockIdx.x * 8 + w;
    float4 xv = *(const float4*)&xin[(size_t)n * Fd + lane * 4];
#pragma unroll
    for (int r = 0; r < Rr; r++) {
        float4 q4 = *(const float4*)&sq[r][lane * 4];
        float4 k4 = *(const float4*)&sk[r][lane * 4];
        float qs = xv.x * q4.x + xv.y * q4.y + xv.z * q4.z + xv.w * q4.w;
        float ks = xv.x * k4.x + xv.y * k4.y + xv.z * k4.z + xv.w * k4.w;
#pragma unroll
        for (int o = 16; o; o >>= 1) {
            qs += __shfl_xor_sync(0xffffffffu, qs, o);
            ks += __shfl_xor_sync(0xffffffffu, ks, o);
        }
        if (lane == 0) { g_qx[n * Rr + r] = qs; g_kx[n * Rr + r] = ks; }
    }
}

// ---------------- fused edge kernel: BLOCK(128) per dst, feature-parallel ----------------
#define ECASE(rr, xv, wt) case rr: acc##rr = fmaf(wt, xv, acc##rr); break;
#define ESW(ev, xv, wv) switch (ev) { \
    ECASE(0, xv, wv) ECASE(1, xv, wv) ECASE(2, xv, wv) ECASE(3, xv, wv) \
    ECASE(4, xv, wv) ECASE(5, xv, wv) ECASE(6, xv, wv) ECASE(7, xv, wv) }

__global__ __launch_bounds__(128) void edge_kernel(const float* __restrict__ xin) {
    const int d = blockIdx.x;
    const int tid = threadIdx.x, wid = tid >> 5, lane = tid & 31;
    __shared__ float sw[128];
    __shared__ int   ssrc[128];
    __shared__ int   sett[128];
    __shared__ float red[4];

    const int beg = g_rowptr[d], end = g_rowptr[d + 1];
    float acc0 = 0.f, acc1 = 0.f, acc2 = 0.f, acc3 = 0.f;
    float acc4 = 0.f, acc5 = 0.f, acc6 = 0.f, acc7 = 0.f;
    float m = -1e30f, s = 0.f;

    for (int j0 = beg; j0 < end; j0 += 128) {
        const int cnt = min(128, end - j0);
        float a = -1e30f;
        int src = 0, et = 0;
        if (tid < cnt) {
            src = g_esrc[j0 + tid];
            et  = g_eet[j0 + tid];
            a = g_qx[d * Rr + et] + g_kx[src * Rr + et];
            a = (a >= 0.f) ? a : 0.2f * a;
        }
        ssrc[tid] = src;
        sett[tid] = et;
        float gm = a;
#pragma unroll
        for (int o = 16; o; o >>= 1) gm = fmaxf(gm, __shfl_xor_sync(0xffffffffu, gm, o));
        if (lane == 0) red[wid] = gm;
        __syncthreads();
        gm = fmaxf(fmaxf(red[0], red[1]), fmaxf(red[2], red[3]));
        if (gm > m) {
            float sc = __expf(m - gm);
            s *= sc;
            acc0 *= sc; acc1 *= sc; acc2 *= sc; acc3 *= sc;
            acc4 *= sc; acc5 *= sc; acc6 *= sc; acc7 *= sc;
            m = gm;
        }
        float w = (tid < cnt) ? __expf(a - m) : 0.f;
        sw[tid] = w;
        float ws = w;
#pragma unroll
        for (int o = 16; o; o >>= 1) ws += __shfl_xor_sync(0xffffffffu, ws, o);
        __syncthreads();
        if (lane == 0) red[wid] = ws;
        __syncthreads();
        s += red[0] + red[1] + red[2] + red[3];

        // feature-parallel accumulate, 4-edge unroll for MLP
        int t = 0;
        for (; t + 4 <= cnt; t += 4) {
            float w0 = sw[t],     w1 = sw[t + 1], w2 = sw[t + 2], w3 = sw[t + 3];
            int   s0 = ssrc[t],   s1 = ssrc[t + 1], s2 = ssrc[t + 2], s3 = ssrc[t + 3];
            int   e0 = sett[t],   e1 = sett[t + 1], e2 = sett[t + 2], e3 = sett[t + 3];
            float x0 = __ldg(&xin[(size_t)s0 * Fd + tid]);
            float x1 = __ldg(&xin[(size_t)s1 * Fd + tid]);
            float x2 = __ldg(&xin[(size_t)s2 * Fd + tid]);
            float x3 = __ldg(&xin[(size_t)s3 * Fd + tid]);
            ESW(e0, x0, w0) ESW(e1, x1, w1) ESW(e2, x2, w2) ESW(e3, x3, w3)
        }
        for (; t < cnt; t++) {
            float wt = sw[t];
            float xv = __ldg(&xin[(size_t)ssrc[t] * Fd + tid]);
            ESW(sett[t], xv, wt)
        }
        __syncthreads();
    }

    float inv = (end > beg) ? (1.f / s) : 0.f;
#define STORE_R(rr, accv) { float v = (accv) * inv; \
    __nv_bfloat16 hi = __float2bfloat16(v); \
    __nv_bfloat16 lo = __float2bfloat16(v - __bfloat162float(hi)); \
    g_aggH[(size_t)d * RH + rr * Hd + tid] = hi; \
    g_aggL[(size_t)d * RH + rr * Hd + tid] = lo; }
    STORE_R(0, acc0) STORE_R(1, acc1) STORE_R(2, acc2) STORE_R(3, acc3)
    STORE_R(4, acc4) STORE_R(5, acc5) STORE_R(6, acc6) STORE_R(7, acc7)
#undef STORE_R
}

// ---------------- cp.async double-buffered bf16 3-pass GEMM ----------------
// h = relu(agg[N,1024] @ Wcat^T + b), operands pre-split bf16 hi/lo in gmem.
#define KC 64
#define NKC (RH / KC)                 // 16
#define SSTR 72
#define STG_BYTES (128 * SSTR * 2)    // 18432 per operand array
#define OFF_AH 0
#define OFF_AL STG_BYTES
#define OFF_BH (2 * STG_BYTES)
#define OFF_BL (3 * STG_BYTES)
#define SM_STAGE (4 * STG_BYTES)      // 73728
#define SM_TOTAL (2 * SM_STAGE)       // 147456

__global__ __launch_bounds__(256) void gemm_mma_kernel(const float* __restrict__ bias,
                                                       float* __restrict__ hout) {
    extern __shared__ __align__(128) char smem[];
    const int tid = threadIdx.x, wid = tid >> 5, lane = tid & 31;
    const int row0 = blockIdx.x * 128;
    const int wr = wid >> 2, wc = wid & 3;
    const uint32_t sb = smem_u32(smem);

    float acc[4][4][4] = {};

    auto copy_chunk = [&](int kc, int buf) {
        const int kbase = kc * KC;
        const uint32_t sbase = sb + buf * SM_STAGE;
#pragma unroll
        for (int i = 0; i < 4; i++) {
            int cid = tid + i * 256;          // 0..1023
            int row = cid >> 3;               // 0..127
            int k8  = (cid & 7) * 8;          // 0..56
            uint32_t so = sbase + (uint32_t)(row * SSTR + k8) * 2;
            int gr = row0 + row;
            int grc = (gr < Nn) ? gr : (Nn - 1);
            int sz = (gr < Nn) ? 16 : 0;
            size_t aidx = (size_t)grc * RH + kbase + k8;
            cp16(so + OFF_AH, &g_aggH[aidx], sz);
            cp16(so + OFF_AL, &g_aggL[aidx], sz);
            size_t bidx = (size_t)row * RH + kbase + k8;
            cp16(so + OFF_BH, &g_Wbh[bidx], 16);
            cp16(so + OFF_BL, &g_Wbl[bidx], 16);
        }
        asm volatile("cp.async.commit_group;");
    };

    copy_chunk(0, 0);
    for (int kc = 0; kc < NKC; kc++) {
        const int buf = kc & 1;
        if (kc + 1 < NKC) {
            copy_chunk(kc + 1, buf ^ 1);
            asm volatile("cp.async.wait_group 1;");
        } else {
            asm volatile("cp.async.wait_group 0;");
        }
        __syncthreads();

        const uint32_t sbase = sb + buf * SM_STAGE;
#pragma unroll
        for (int ks = 0; ks < 4; ks++) {
            const int k0 = ks * 16;
            const uint32_t lrow = lane & 15;
            const uint32_t lcol = (k0 + ((lane >> 4) << 3)) * 2;
            uint32_t ah[4][4], al[4][4], bh[2][4], bl[2][4];
#pragma unroll
            for (int mt = 0; mt < 4; mt++) {
                uint32_t base = sbase + (wr * 64 + mt * 16 + lrow) * (SSTR * 2) + lcol;
                ldsm_x4(ah[mt], base + OFF_AH);
                ldsm_x4(al[mt], base + OFF_AL);
            }
#pragma unroll
            for (int p = 0; p < 2; p++) {
                uint32_t base = sbase + (wc * 32 + p * 16 + lrow) * (SSTR * 2) + lcol;
                ldsm_x4(bh[p], base + OFF_BH);
                ldsm_x4(bl[p], base + OFF_BL);
            }
#pragma unroll
            for (int mt = 0; mt < 4; mt++)
#pragma unroll
                for (int p = 0; p < 2; p++)
#pragma unroll
                    for (int q = 0; q < 2; q++) {
                        float* c = acc[mt][p * 2 + q];
                        mma_bf16(c, ah[mt], bh[p][q], bh[p][q + 2]);
                        mma_bf16(c, ah[mt], bl[p][q], bl[p][q + 2]);
                        mma_bf16(c, al[mt], bh[p][q], bh[p][q + 2]);
                    }
        }
        __syncthreads();
    }

    // stage accumulators -> smem
    float (*stage)[132] = (float(*)[132])smem;
#pragma unroll
    for (int mt = 0; mt < 4; mt++)
#pragma unroll
        for (int nt = 0; nt < 4; nt++) {
            int rr = wr * 64 + mt * 16 + (lane >> 2);
            int cc = wc * 32 + nt * 8 + (lane & 3) * 2;
            stage[rr][cc]     = acc[mt][nt][0];
            stage[rr][cc + 1] = acc[mt][nt][1];
            stage[rr + 8][cc]     = acc[mt][nt][2];
            stage[rr + 8][cc + 1] = acc[mt][nt][3];
        }
    __syncthreads();

    // bias + relu + coalesced store
#pragma unroll
    for (int i = 0; i < 16; i++) {
        int cid = tid + i * 256;
        int row = cid >> 5;
        int c4  = (cid & 31) * 4;
        int node = row0 + row;
        if (node < Nn) {
            float4 v = *(const float4*)&stage[row][c4];
            v.x = fmaxf(v.x + __ldg(&bias[c4]),     0.f);
            v.y = fmaxf(v.y + __ldg(&bias[c4 + 1]), 0.f);
            v.z = fmaxf(v.z + __ldg(&bias[c4 + 2]), 0.f);
            v.w = fmaxf(v.w + __ldg(&bias[c4 + 3]), 0.f);
            *(float4*)&hout[(size_t)node * Hd + c4] = v;
        }
    }
}

// ---------------- final linear + log_softmax ----------------
__global__ __launch_bounds__(256) void final_kernel(const float* __restrict__ h,
                                                    const float* __restrict__ lw,
                                                    const float* __restrict__ lb,
                                                    float* __restrict__ out) {
    __shared__ float sh[8][Hd];
    int tid = threadIdx.x;
    int nodeBase = blockIdx.x * 8;
#pragma unroll
    for (int l = 0; l < 4; l++) {
        int idx = tid + l * 256;
        sh[idx >> 7][idx & 127] = h[(size_t)nodeBase * Hd + idx];
    }
    __syncthreads();
    int w = tid >> 5, lane = tid & 31;
    int n = nodeBase + w;
    float a0 = lb[lane], a1 = lb[lane + 32];
#pragma unroll 16
    for (int f = 0; f < Hd; f++) {
        float hv = sh[w][f];
        a0 = fmaf(hv, lw[f * Cc + lane], a0);
        a1 = fmaf(hv, lw[f * Cc + lane + 32], a1);
    }
    float mx = fmaxf(a0, a1);
#pragma unroll
    for (int o = 16; o; o >>= 1) mx = fmaxf(mx, __shfl_xor_sync(0xffffffffu, mx, o));
    float s = expf(a0 - mx) + expf(a1 - mx);
#pragma unroll
    for (int o = 16; o; o >>= 1) s += __shfl_xor_sync(0xffffffffu, s, o);
    float lse = mx + logf(s);
    out[(size_t)n * Cc + lane]      = a0 - lse;
    out[(size_t)n * Cc + lane + 32] = a1 - lse;
}

// ---------------- host orchestration ----------------
static void run_layer(const float* xin, const float* W, const float* q,
                      const float* k, const float* b, float* hout) {
    wqk_kernel<<<(Rr * Fd * 32 + 255) / 256, 256>>>(W, q, k);
    wprep_kernel<<<dim3(4, 4, 8), dim3(32, 8)>>>(W);
    qxkx_kernel<<<Nn / 8, 256>>>(xin);
    edge_kernel<<<Nn, 128>>>(xin);
    gemm_mma_kernel<<<(Nn + 127) / 128, 256, SM_TOTAL>>>(b, hout);
}

extern "C" void kernel_launch(void* const* d_in, const int* in_sizes, int n_in,
                              void* d_out, int out_size) {
    const float* x     = (const float*)d_in[0];
    const void*  ei    = d_in[1];
    const void*  et    = d_in[2];
    const float* W1    = (const float*)d_in[3];
    const float* q1    = (const float*)d_in[4];
    const float* k1    = (const float*)d_in[5];
    const float* b1    = (const float*)d_in[6];
    const float* W2    = (const float*)d_in[7];
    const float* q2    = (const float*)d_in[8];
    const float* k2    = (const float*)d_in[9];
    const float* b2    = (const float*)d_in[10];
    const float* W3    = (const float*)d_in[11];
    const float* q3    = (const float*)d_in[12];
    const float* k3    = (const float*)d_in[13];
    const float* b3    = (const float*)d_in[14];
    const float* lin_w = (const float*)d_in[15];
    const float* lin_b = (const float*)d_in[16];

    cudaFuncSetAttribute(gemm_mma_kernel,
                         cudaFuncAttributeMaxDynamicSharedMemorySize, SM_TOTAL);

    float *hA = nullptr, *hB = nullptr;
    cudaGetSymbolAddress((void**)&hA, g_hA);
    cudaGetSymbolAddress((void**)&hB, g_hB);

    detect_kernel<<<1, 32>>>((const unsigned*)ei);
    convert_kernel<<<(Ee + 255) / 256, 256>>>(ei, et);

    // CSR build (once per launch)
    zero_kernel<<<(Nn + 255) / 256, 256>>>();
    hist_kernel<<<(Ee + 255) / 256, 256>>>();
    scan1_kernel<<<NB, SCANB>>>();
    scan2_kernel<<<1, 32>>>();
    scan3_kernel<<<(Nn + 255) / 256, 256>>>();
    scatter_kernel<<<(Ee + 255) / 256, 256>>>();

    run_layer(x,  W1, q1, k1, b1, hA);
    run_layer(hA, W2, q2, k2, b2, hB);
    run_layer(hB, W3, q3, k3, b3, hA);

    final_kernel<<<Nn / 8, 256>>>(hA, lin_w, lin_b, (float*)d_out);
}

// round 7
// speedup vs baseline: 1.3339x; 1.0021x over previous
#include <cuda_runtime.h>
#include <cuda_bf16.h>
#include <cstdint>

#define Nn 50000
#define Ee 800000
#define Rr 8
#define Fd 128
#define Hd 128
#define Cc 64
#define RH (Rr * Hd)   // 1024
#define NK (Nn * Rr)   // 400000 segment keys
#define SCANB 512
#define NB2 ((NK + SCANB - 1) / SCANB)   // 782

// ---------------- device scratch ----------------
__device__ __nv_bfloat16 g_aggH[(size_t)Nn * RH];  // aggregated features hi
__device__ __nv_bfloat16 g_aggL[(size_t)Nn * RH];  // lo
__device__ float         g_hA[Nn * Hd];
__device__ float         g_hB[Nn * Hd];
__device__ float         g_qx[Nn * Rr];
__device__ float         g_kx[Nn * Rr];
__device__ __nv_bfloat16 g_Wbh[Hd * RH];   // Wcat [h][r*128+f] hi
__device__ __nv_bfloat16 g_Wbl[Hd * RH];   // lo
__device__ float         g_Wq[Rr * Fd];
__device__ float         g_Wk[Rr * Fd];
__device__ int           g_src[Ee];
__device__ int           g_dst[Ee];
__device__ int           g_et[Ee];
__device__ int           g_esrc[Ee];       // sorted by key = dst*8+et
__device__ int           g_rp2[NK + 1];
__device__ int           g_rpp[NK];
__device__ int           g_bsum[NB2];
__device__ int           g_cnt[NK];
__device__ int           g_fill[NK];
__device__ int           g_is64;

// ---------------- helpers ----------------
__device__ __forceinline__ uint32_t smem_u32(const void* p) {
    uint32_t a;
    asm("{ .reg .u64 t; cvta.to.shared.u64 t, %1; cvt.u32.u64 %0, t; }" : "=r"(a) : "l"(p));
    return a;
}
__device__ __forceinline__ void ldsm_x4(uint32_t* r, uint32_t addr) {
    asm volatile("ldmatrix.sync.aligned.m8n8.x4.shared.b16 {%0,%1,%2,%3}, [%4];"
                 : "=r"(r[0]), "=r"(r[1]), "=r"(r[2]), "=r"(r[3]) : "r"(addr));
}
__device__ __forceinline__ void mma_bf16(float* c, const uint32_t* a, uint32_t b0, uint32_t b1) {
    asm volatile(
        "mma.sync.aligned.m16n8k16.row.col.f32.bf16.bf16.f32 "
        "{%0,%1,%2,%3}, {%4,%5,%6,%7}, {%8,%9}, {%0,%1,%2,%3};"
        : "+f"(c[0]), "+f"(c[1]), "+f"(c[2]), "+f"(c[3])
        : "r"(a[0]), "r"(a[1]), "r"(a[2]), "r"(a[3]), "r"(b0), "r"(b1));
}
__device__ __forceinline__ void cp16(uint32_t saddr, const void* g, int srcsize) {
    asm volatile("cp.async.cg.shared.global [%0], [%1], 16, %2;"
                 :: "r"(saddr), "l"(g), "r"(srcsize));
}

// ---------------- dtype detect + edge conversion ----------------
__global__ void detect_kernel(const unsigned* __restrict__ ei) {
    if (threadIdx.x == 0 && blockIdx.x == 0) {
        int zeros = 0;
        for (int i = 0; i < 128; i++)
            if (ei[2 * i + 1] == 0u) zeros++;
        g_is64 = (zeros == 128) ? 1 : 0;
    }
}

__global__ void convert_kernel(const void* __restrict__ ei, const void* __restrict__ et) {
    int e = blockIdx.x * blockDim.x + threadIdx.x;
    if (e >= Ee) return;
    if (g_is64) {
        const long long* p = (const long long*)ei;
        g_src[e] = (int)p[e];
        g_dst[e] = (int)p[Ee + e];
        g_et[e]  = (int)((const long long*)et)[e];
    } else {
        const int* p = (const int*)ei;
        g_src[e] = p[e];
        g_dst[e] = p[Ee + e];
        g_et[e]  = ((const int*)et)[e];
    }
}

// ---------------- CSR build keyed by (dst*8 + et) ----------------
__global__ void zero_kernel() {
    int i = blockIdx.x * blockDim.x + threadIdx.x;
    if (i < NK) { g_cnt[i] = 0; g_fill[i] = 0; }
}
__global__ void hist_kernel() {
    int e = blockIdx.x * blockDim.x + threadIdx.x;
    if (e < Ee) atomicAdd(&g_cnt[g_dst[e] * Rr + g_et[e]], 1);
}
__global__ void scan1_kernel() {
    __shared__ int ss[SCANB];
    int t = threadIdx.x;
    int idx = blockIdx.x * SCANB + t;
    int v = (idx < NK) ? g_cnt[idx] : 0;
    ss[t] = v;
    __syncthreads();
    for (int off = 1; off < SCANB; off <<= 1) {
        int tmp = (t >= off) ? ss[t - off] : 0;
        __syncthreads();
        ss[t] += tmp;
        __syncthreads();
    }
    if (idx < NK) g_rpp[idx] = ss[t] - v;
    if (t == SCANB - 1) g_bsum[blockIdx.x] = ss[t];
}
// parallel exclusive scan of the 782 block sums (single block)
__global__ void scan2_kernel() {
    __shared__ int ss[1024];
    int t = threadIdx.x;
    int v = (t < NB2) ? g_bsum[t] : 0;
    ss[t] = v;
    __syncthreads();
    for (int off = 1; off < 1024; off <<= 1) {
        int tmp = (t >= off) ? ss[t - off] : 0;
        __syncthreads();
        ss[t] += tmp;
        __syncthreads();
    }
    if (t < NB2) g_bsum[t] = ss[t] - v;      // exclusive
    if (t == 1023) g_rp2[NK] = ss[t];        // total = Ee
}
__global__ void scan3_kernel() {
    int idx = blockIdx.x * blockDim.x + threadIdx.x;
    if (idx < NK) g_rp2[idx] = g_rpp[idx] + g_bsum[idx >> 9];
}
__global__ void scatter_kernel() {
    int e = blockIdx.x * blockDim.x + threadIdx.x;
    if (e >= Ee) return;
    int key = g_dst[e] * Rr + g_et[e];
    int p = g_rp2[key] + atomicAdd(&g_fill[key], 1);
    g_esrc[p] = g_src[e];
}

// ---------------- weight prep ----------------
__global__ void wqk_kernel(const float* __restrict__ W,
                           const float* __restrict__ q,
                           const float* __restrict__ k) {
    int warp = (blockIdx.x * blockDim.x + threadIdx.x) >> 5;
    int lane = threadIdx.x & 31;
    if (warp >= Rr * Fd) return;
    const float* wrow = W + (size_t)warp * Hd;
    float sq = 0.f, sk = 0.f;
#pragma unroll
    for (int j = 0; j < 4; j++) {
        float wv = wrow[lane + 32 * j];
        sq += wv * q[lane + 32 * j];
        sk += wv * k[lane + 32 * j];
    }
#pragma unroll
    for (int o = 16; o; o >>= 1) {
        sq += __shfl_xor_sync(0xffffffffu, sq, o);
        sk += __shfl_xor_sync(0xffffffffu, sk, o);
    }
    if (lane == 0) { g_Wq[warp] = sq; g_Wk[warp] = sk; }
}

// tiled transpose: W[r,f,h] -> Wcat[h][r*128+f] bf16 hi/lo, coalesced
__global__ void wprep_kernel(const float* __restrict__ W) {
    __shared__ float t[32][33];
    int r = blockIdx.z, f0 = blockIdx.x * 32, h0 = blockIdx.y * 32;
    int tx = threadIdx.x, ty = threadIdx.y;   // 32 x 8
#pragma unroll
    for (int i = 0; i < 4; i++) {
        int f = f0 + ty + i * 8;
        t[ty + i * 8][tx] = W[(size_t)r * Fd * Hd + (size_t)f * Hd + h0 + tx];
    }
    __syncthreads();
#pragma unroll
    for (int i = 0; i < 4; i++) {
        int h = h0 + ty + i * 8;
        float v = t[tx][ty + i * 8];
        __nv_bfloat16 hi = __float2bfloat16(v);
        __nv_bfloat16 lo = __float2bfloat16(v - __bfloat162float(hi));
        size_t oidx = (size_t)h * RH + r * Hd + f0 + tx;
        g_Wbh[oidx] = hi;
        g_Wbl[oidx] = lo;
    }
}

// ---------------- qx/kx: warp per node ----------------
__global__ __launch_bounds__(256) void qxkx_kernel(const float* __restrict__ xin) {
    __shared__ float sq[Rr][Fd], sk[Rr][Fd];
    int tid = threadIdx.x;
    for (int i = tid; i < Rr * Fd; i += 256) {
        sq[i >> 7][i & 127] = g_Wq[i];
        sk[i >> 7][i & 127] = g_Wk[i];
    }
    __syncthreads();
    int w = tid >> 5, lane = tid & 31;
    int n = blockIdx.x * 8 + w;
    float4 xv = *(const float4*)&xin[(size_t)n * Fd + lane * 4];
#pragma unroll
    for (int r = 0; r < Rr; r++) {
        float4 q4 = *(const float4*)&sq[r][lane * 4];
        float4 k4 = *(const float4*)&sk[r][lane * 4];
        float qs = xv.x * q4.x + xv.y * q4.y + xv.z * q4.z + xv.w * q4.w;
        float ks = xv.x * k4.x + xv.y * k4.y + xv.z * k4.z + xv.w * k4.w;
#pragma unroll
        for (int o = 16; o; o >>= 1) {
            qs += __shfl_xor_sync(0xffffffffu, qs, o);
            ks += __shfl_xor_sync(0xffffffffu, ks, o);
        }
        if (lane == 0) { g_qx[n * Rr + r] = qs; g_kx[n * Rr + r] = ks; }
    }
}

// ---------------- fused edge kernel: block(128)/dst, et-segmented, branch-free ----------------
__global__ __launch_bounds__(128) void edge_kernel(const float* __restrict__ xin) {
    const int d = blockIdx.x;
    const int tid = threadIdx.x, wid = tid >> 5, lane = tid & 31;
    __shared__ float sw[128];
    __shared__ int   ssrc[128];
    __shared__ int   sb8[9];
    __shared__ float red[4];

    if (tid < 9) sb8[tid] = g_rp2[d * Rr + tid];
    __syncthreads();
    const int beg = sb8[0], end = sb8[8];

    float acc[Rr] = {};
    float m = -1e30f, s = 0.f;

    for (int j0 = beg; j0 < end; j0 += 128) {
        const int cnt = min(128, end - j0);
        float a = -1e30f;
        int src = 0;
        if (tid < cnt) {
            int j = j0 + tid;
            src = g_esrc[j];
            int et = 0;
#pragma unroll
            for (int r = 1; r < Rr; r++) et += (j >= sb8[r]);
            a = g_qx[d * Rr + et] + g_kx[src * Rr + et];
            a = (a >= 0.f) ? a : 0.2f * a;
        }
        ssrc[tid] = src;
        float gm = a;
#pragma unroll
        for (int o = 16; o; o >>= 1) gm = fmaxf(gm, __shfl_xor_sync(0xffffffffu, gm, o));
        if (lane == 0) red[wid] = gm;
        __syncthreads();
        gm = fmaxf(fmaxf(red[0], red[1]), fmaxf(red[2], red[3]));
        if (gm > m) {
            float sc = __expf(m - gm);
            s *= sc;
#pragma unroll
            for (int r = 0; r < Rr; r++) acc[r] *= sc;
            m = gm;
        }
        float w = (tid < cnt) ? __expf(a - m) : 0.f;
        sw[tid] = w;
        float ws = w;
#pragma unroll
        for (int o = 16; o; o >>= 1) ws += __shfl_xor_sync(0xffffffffu, ws, o);
        __syncthreads();
        if (lane == 0) red[wid] = ws;
        __syncthreads();
        s += red[0] + red[1] + red[2] + red[3];

        // branch-free per-relation accumulate (segments contiguous within chunk)
#pragma unroll
        for (int r = 0; r < Rr; r++) {
            int lo = max(j0, sb8[r]) - j0;
            int hi = min(j0 + cnt, sb8[r + 1]) - j0;
            float ar = 0.f;
            int t = lo;
            for (; t + 2 <= hi; t += 2) {
                float x0 = __ldg(&xin[(size_t)ssrc[t] * Fd + tid]);
                float x1 = __ldg(&xin[(size_t)ssrc[t + 1] * Fd + tid]);
                ar = fmaf(sw[t], x0, ar);
                ar = fmaf(sw[t + 1], x1, ar);
            }
            if (t < hi)
                ar = fmaf(sw[t], __ldg(&xin[(size_t)ssrc[t] * Fd + tid]), ar);
            acc[r] += ar;
        }
        __syncthreads();
    }

    float inv = (end > beg) ? (1.f / s) : 0.f;
#pragma unroll
    for (int r = 0; r < Rr; r++) {
        float v = acc[r] * inv;
        __nv_bfloat16 hi = __float2bfloat16(v);
        __nv_bfloat16 lo = __float2bfloat16(v - __bfloat162float(hi));
        g_aggH[(size_t)d * RH + r * Hd + tid] = hi;
        g_aggL[(size_t)d * RH + r * Hd + tid] = lo;
    }
}

// ---------------- cp.async double-buffered bf16 3-pass GEMM, 2 CTAs/SM ----------------
#define KC 32
#define NKC (RH / KC)                 // 32
#define SSTR 40                       // 32 + 8 pad elems (80 B rows, ldsm conflict-free)
#define STG_BYTES (128 * SSTR * 2)    // 10240
#define OFF_AH 0
#define OFF_AL STG_BYTES
#define OFF_BH (2 * STG_BYTES)
#define OFF_BL (3 * STG_BYTES)
#define SM_STAGE (4 * STG_BYTES)      // 40960
#define SM_TOTAL (2 * SM_STAGE)       // 81920

__global__ __launch_bounds__(256, 2) void gemm_mma_kernel(const float* __restrict__ bias,
                                                          float* __restrict__ hout) {
    extern __shared__ __align__(128) char smem[];
    const int tid = threadIdx.x, wid = tid >> 5, lane = tid & 31;
    const int row0 = blockIdx.x * 128;
    const int wr = wid >> 2, wc = wid & 3;
    const uint32_t sb = smem_u32(smem);

    float acc[4][4][4] = {};

    auto copy_chunk = [&](int kc, int buf) {
        const int kbase = kc * KC;
        const uint32_t sbase = sb + buf * SM_STAGE;
#pragma unroll
        for (int i = 0; i < 2; i++) {
            int cid = tid + i * 256;          // 0..511
            int row = cid >> 2;               // 0..127
            int k8  = (cid & 3) * 8;          // 0..24
            uint32_t so = sbase + (uint32_t)(row * SSTR + k8) * 2;
            int gr = row0 + row;
            int grc = (gr < Nn) ? gr : (Nn - 1);
            int sz = (gr < Nn) ? 16 : 0;
            size_t aidx = (size_t)grc * RH + kbase + k8;
            cp16(so + OFF_AH, &g_aggH[aidx], sz);
            cp16(so + OFF_AL, &g_aggL[aidx], sz);
            size_t bidx = (size_t)row * RH + kbase + k8;
            cp16(so + OFF_BH, &g_Wbh[bidx], 16);
            cp16(so + OFF_BL, &g_Wbl[bidx], 16);
        }
        asm volatile("cp.async.commit_group;");
    };

    copy_chunk(0, 0);
    for (int kc = 0; kc < NKC; kc++) {
        const int buf = kc & 1;
        if (kc + 1 < NKC) {
            copy_chunk(kc + 1, buf ^ 1);
            asm volatile("cp.async.wait_group 1;");
        } else {
            asm volatile("cp.async.wait_group 0;");
        }
        __syncthreads();

        const uint32_t sbase = sb + buf * SM_STAGE;
#pragma unroll
        for (int ks = 0; ks < 2; ks++) {
            const int k0 = ks * 16;
            const uint32_t lrow = lane & 15;
            const uint32_t lcol = (k0 + ((lane >> 4) << 3)) * 2;
            uint32_t ah[4][4], al[4][4], bh[2][4], bl[2][4];
#pragma unroll
            for (int mt = 0; mt < 4; mt++) {
                uint32_t base = sbase + (wr * 64 + mt * 16 + lrow) * (SSTR * 2) + lcol;
                ldsm_x4(ah[mt], base + OFF_AH);
                ldsm_x4(al[mt], base + OFF_AL);
            }
#pragma unroll
            for (int p = 0; p < 2; p++) {
                uint32_t base = sbase + (wc * 32 + p * 16 + lrow) * (SSTR * 2) + lcol;
                ldsm_x4(bh[p], base + OFF_BH);
                ldsm_x4(bl[p], base + OFF_BL);
            }
#pragma unroll
            for (int mt = 0; mt < 4; mt++)
#pragma unroll
                for (int p = 0; p < 2; p++)
#pragma unroll
                    for (int q = 0; q < 2; q++) {
                        float* c = acc[mt][p * 2 + q];
                        mma_bf16(c, ah[mt], bh[p][q], bh[p][q + 2]);
                        mma_bf16(c, ah[mt], bl[p][q], bl[p][q + 2]);
                        mma_bf16(c, al[mt], bh[p][q], bh[p][q + 2]);
                    }
        }
        __syncthreads();
    }

    // stage accumulators -> smem (67584 B, fits in 81920)
    float (*stage)[132] = (float(*)[132])smem;
#pragma unroll
    for (int mt = 0; mt < 4; mt++)
#pragma unroll
        for (int nt = 0; nt < 4; nt++) {
            int rr = wr * 64 + mt * 16 + (lane >> 2);
            int cc = wc * 32 + nt * 8 + (lane & 3) * 2;
            stage[rr][cc]     = acc[mt][nt][0];
            stage[rr][cc + 1] = acc[mt][nt][1];
            stage[rr + 8][cc]     = acc[mt][nt][2];
            stage[rr + 8][cc + 1] = acc[mt][nt][3];
        }
    __syncthreads();

    // bias + relu + coalesced store
#pragma unroll
    for (int i = 0; i < 16; i++) {
        int cid = tid + i * 256;
        int row = cid >> 5;
        int c4  = (cid & 31) * 4;
        int node = row0 + row;
        if (node < Nn) {
            float4 v = *(const float4*)&stage[row][c4];
            v.x = fmaxf(v.x + __ldg(&bias[c4]),     0.f);
            v.y = fmaxf(v.y + __ldg(&bias[c4 + 1]), 0.f);
            v.z = fmaxf(v.z + __ldg(&bias[c4 + 2]), 0.f);
            v.w = fmaxf(v.w + __ldg(&bias[c4 + 3]), 0.f);
            *(float4*)&hout[(size_t)node * Hd + c4] = v;
        }
    }
}

// ---------------- final linear + log_softmax ----------------
__global__ __launch_bounds__(256) void final_kernel(const float* __restrict__ h,
                                                    const float* __restrict__ lw,
                                                    const float* __restrict__ lb,
                                                    float* __restrict__ out) {
    __shared__ float sh[8][Hd];
    int tid = threadIdx.x;
    int nodeBase = blockIdx.x * 8;
#pragma unroll
    for (int l = 0; l < 4; l++) {
        int idx = tid + l * 256;
        sh[idx >> 7][idx & 127] = h[(size_t)nodeBase * Hd + idx];
    }
    __syncthreads();
    int w = tid >> 5, lane = tid & 31;
    int n = nodeBase + w;
    float a0 = lb[lane], a1 = lb[lane + 32];
#pragma unroll 16
    for (int f = 0; f < Hd; f++) {
        float hv = sh[w][f];
        a0 = fmaf(hv, lw[f * Cc + lane], a0);
        a1 = fmaf(hv, lw[f * Cc + lane + 32], a1);
    }
    float mx = fmaxf(a0, a1);
#pragma unroll
    for (int o = 16; o; o >>= 1) mx = fmaxf(mx, __shfl_xor_sync(0xffffffffu, mx, o));
    float s = expf(a0 - mx) + expf(a1 - mx);
#pragma unroll
    for (int o = 16; o; o >>= 1) s += __shfl_xor_sync(0xffffffffu, s, o);
    float lse = mx + logf(s);
    out[(size_t)n * Cc + lane]      = a0 - lse;
    out[(size_t)n * Cc + lane + 32] = a1 - lse;
}

// ---------------- host orchestration ----------------
static void run_layer(const float* xin, const float* W, const float* q,
                      const float* k, const float* b, float* hout) {
    wqk_kernel<<<(Rr * Fd * 32 + 255) / 256, 256>>>(W, q, k);
    wprep_kernel<<<dim3(4, 4, 8), dim3(32, 8)>>>(W);
    qxkx_kernel<<<Nn / 8, 256>>>(xin);
    edge_kernel<<<Nn, 128>>>(xin);
    gemm_mma_kernel<<<(Nn + 127) / 128, 256, SM_TOTAL>>>(b, hout);
}

extern "C" void kernel_launch(void* const* d_in, const int* in_sizes, int n_in,
                              void* d_out, int out_size) {
    const float* x     = (const float*)d_in[0];
    const void*  ei    = d_in[1];
    const void*  et    = d_in[2];
    const float* W1    = (const float*)d_in[3];
    const float* q1    = (const float*)d_in[4];
    const float* k1    = (const float*)d_in[5];
    const float* b1    = (const float*)d_in[6];
    const float* W2    = (const float*)d_in[7];
    const float* q2    = (const float*)d_in[8];
    const float* k2    = (const float*)d_in[9];
    const float* b2    = (const float*)d_in[10];
    const float* W3    = (const float*)d_in[11];
    const float* q3    = (const float*)d_in[12];
    const float* k3    = (const float*)d_in[13];
    const float* b3    = (const float*)d_in[14];
    const float* lin_w = (const float*)d_in[15];
    const float* lin_b = (const float*)d_in[16];

    cudaFuncSetAttribute(gemm_mma_kernel,
                         cudaFuncAttributeMaxDynamicSharedMemorySize, SM_TOTAL);

    float *hA = nullptr, *hB = nullptr;
    cudaGetSymbolAddress((void**)&hA, g_hA);
    cudaGetSymbolAddress((void**)&hB, g_hB);

    detect_kernel<<<1, 32>>>((const unsigned*)ei);
    convert_kernel<<<(Ee + 255) / 256, 256>>>(ei, et);

    // CSR build keyed by (dst, et), once per launch
    zero_kernel<<<(NK + 255) / 256, 256>>>();
    hist_kernel<<<(Ee + 255) / 256, 256>>>();
    scan1_kernel<<<NB2, SCANB>>>();
    scan2_kernel<<<1, 1024>>>();
    scan3_kernel<<<(NK + 255) / 256, 256>>>();
    scatter_kernel<<<(Ee + 255) / 256, 256>>>();

    run_layer(x,  W1, q1, k1, b1, hA);
    run_layer(hA, W2, q2, k2, b2, hB);
    run_layer(hB, W3, q3, k3, b3, hA);

    final_kernel<<<Nn / 8, 256>>>(hA, lin_w, lin_b, (float*)d_out);
}

// round 8
// speedup vs baseline: 1.6003x; 1.1997x over previous
#include <cuda_runtime.h>
#include <cuda_bf16.h>
#include <cstdint>

#define Nn 50000
#define Ee 800000
#define Rr 8
#define Fd 128
#define Hd 128
#define Cc 64
#define RH (Rr * Hd)   // 1024
#define NK (Nn * Rr)   // 400000 segment keys
#define SCANB 512
#define NB2 ((NK + SCANB - 1) / SCANB)   // 782

// ---------------- device scratch ----------------
__device__ __nv_bfloat16 g_aggH[(size_t)Nn * RH];
__device__ __nv_bfloat16 g_aggL[(size_t)Nn * RH];
__device__ float         g_hA[Nn * Hd];
__device__ float         g_hB[Nn * Hd];
__device__ float         g_qx[Nn * Rr];
__device__ float         g_kx[Nn * Rr];
__device__ __nv_bfloat16 g_Wbh[Hd * RH];   // Wcat [h][r*128+f] hi
__device__ __nv_bfloat16 g_Wbl[Hd * RH];   // lo
__device__ float         g_Wq[Rr * Fd];
__device__ float         g_Wk[Rr * Fd];
__device__ int           g_src[Ee];
__device__ int           g_dst[Ee];
__device__ int           g_et[Ee];
__device__ int           g_esrc[Ee];       // sorted by key = dst*8+et
__device__ int           g_eky[Ee];        // key per sorted slot
__device__ float         g_ew[Ee];         // score, then weight
__device__ unsigned      g_mEnc[Nn];
__device__ float         g_s[Nn];
__device__ int           g_rp2[NK + 1];
__device__ int           g_rpp[NK];
__device__ int           g_bsum[NB2];
__device__ int           g_cnt[NK];
__device__ int           g_fill[NK];
__device__ int           g_is64;

// ---------------- helpers ----------------
__device__ __forceinline__ unsigned encf(float f) {
    unsigned u = __float_as_uint(f);
    return (u & 0x80000000u) ? ~u : (u | 0x80000000u);
}
__device__ __forceinline__ float decf(unsigned u) {
    return (u & 0x80000000u) ? __uint_as_float(u & 0x7FFFFFFFu)
                             : __uint_as_float(~u);
}
__device__ __forceinline__ uint32_t smem_u32(const void* p) {
    uint32_t a;
    asm("{ .reg .u64 t; cvta.to.shared.u64 t, %1; cvt.u32.u64 %0, t; }" : "=r"(a) : "l"(p));
    return a;
}
__device__ __forceinline__ void ldsm_x4(uint32_t* r, uint32_t addr) {
    asm volatile("ldmatrix.sync.aligned.m8n8.x4.shared.b16 {%0,%1,%2,%3}, [%4];"
                 : "=r"(r[0]), "=r"(r[1]), "=r"(r[2]), "=r"(r[3]) : "r"(addr));
}
__device__ __forceinline__ void mma_bf16(float* c, const uint32_t* a, uint32_t b0, uint32_t b1) {
    asm volatile(
        "mma.sync.aligned.m16n8k16.row.col.f32.bf16.bf16.f32 "
        "{%0,%1,%2,%3}, {%4,%5,%6,%7}, {%8,%9}, {%0,%1,%2,%3};"
        : "+f"(c[0]), "+f"(c[1]), "+f"(c[2]), "+f"(c[3])
        : "r"(a[0]), "r"(a[1]), "r"(a[2]), "r"(a[3]), "r"(b0), "r"(b1));
}
__device__ __forceinline__ void cp16(uint32_t saddr, const void* g, int srcsize) {
    asm volatile("cp.async.cg.shared.global [%0], [%1], 16, %2;"
                 :: "r"(saddr), "l"(g), "r"(srcsize));
}

// ---------------- dtype detect + edge conversion ----------------
__global__ void detect_kernel(const unsigned* __restrict__ ei) {
    if (threadIdx.x == 0 && blockIdx.x == 0) {
        int zeros = 0;
        for (int i = 0; i < 128; i++)
            if (ei[2 * i + 1] == 0u) zeros++;
        g_is64 = (zeros == 128) ? 1 : 0;
    }
}

__global__ void convert_kernel(const void* __restrict__ ei, const void* __restrict__ et) {
    int e = blockIdx.x * blockDim.x + threadIdx.x;
    if (e >= Ee) return;
    if (g_is64) {
        const long long* p = (const long long*)ei;
        g_src[e] = (int)p[e];
        g_dst[e] = (int)p[Ee + e];
        g_et[e]  = (int)((const long long*)et)[e];
    } else {
        const int* p = (const int*)ei;
        g_src[e] = p[e];
        g_dst[e] = p[Ee + e];
        g_et[e]  = ((const int*)et)[e];
    }
}

// ---------------- CSR build keyed by (dst*8 + et) ----------------
__global__ void zero_kernel() {
    int i = blockIdx.x * blockDim.x + threadIdx.x;
    if (i < NK) { g_cnt[i] = 0; g_fill[i] = 0; }
}
__global__ void hist_kernel() {
    int e = blockIdx.x * blockDim.x + threadIdx.x;
    if (e < Ee) atomicAdd(&g_cnt[g_dst[e] * Rr + g_et[e]], 1);
}
__global__ void scan1_kernel() {
    __shared__ int ss[SCANB];
    int t = threadIdx.x;
    int idx = blockIdx.x * SCANB + t;
    int v = (idx < NK) ? g_cnt[idx] : 0;
    ss[t] = v;
    __syncthreads();
    for (int off = 1; off < SCANB; off <<= 1) {
        int tmp = (t >= off) ? ss[t - off] : 0;
        __syncthreads();
        ss[t] += tmp;
        __syncthreads();
    }
    if (idx < NK) g_rpp[idx] = ss[t] - v;
    if (t == SCANB - 1) g_bsum[blockIdx.x] = ss[t];
}
__global__ void scan2_kernel() {
    __shared__ int ss[1024];
    int t = threadIdx.x;
    int v = (t < NB2) ? g_bsum[t] : 0;
    ss[t] = v;
    __syncthreads();
    for (int off = 1; off < 1024; off <<= 1) {
        int tmp = (t >= off) ? ss[t - off] : 0;
        __syncthreads();
        ss[t] += tmp;
        __syncthreads();
    }
    if (t < NB2) g_bsum[t] = ss[t] - v;
    if (t == 1023) g_rp2[NK] = ss[t];
}
__global__ void scan3_kernel() {
    int idx = blockIdx.x * blockDim.x + threadIdx.x;
    if (idx < NK) g_rp2[idx] = g_rpp[idx] + g_bsum[idx >> 9];
}
__global__ void scatter_kernel() {
    int e = blockIdx.x * blockDim.x + threadIdx.x;
    if (e >= Ee) return;
    int key = g_dst[e] * Rr + g_et[e];
    int p = g_rp2[key] + atomicAdd(&g_fill[key], 1);
    g_esrc[p] = g_src[e];
    g_eky[p]  = key;
}

// ---------------- weight prep ----------------
__global__ void wqk_kernel(const float* __restrict__ W,
                           const float* __restrict__ q,
                           const float* __restrict__ k) {
    int warp = (blockIdx.x * blockDim.x + threadIdx.x) >> 5;
    int lane = threadIdx.x & 31;
    if (warp >= Rr * Fd) return;
    const float* wrow = W + (size_t)warp * Hd;
    float sq = 0.f, sk = 0.f;
#pragma unroll
    for (int j = 0; j < 4; j++) {
        float wv = wrow[lane + 32 * j];
        sq += wv * q[lane + 32 * j];
        sk += wv * k[lane + 32 * j];
    }
#pragma unroll
    for (int o = 16; o; o >>= 1) {
        sq += __shfl_xor_sync(0xffffffffu, sq, o);
        sk += __shfl_xor_sync(0xffffffffu, sk, o);
    }
    if (lane == 0) { g_Wq[warp] = sq; g_Wk[warp] = sk; }
}

__global__ void wprep_kernel(const float* __restrict__ W) {
    __shared__ float t[32][33];
    int r = blockIdx.z, f0 = blockIdx.x * 32, h0 = blockIdx.y * 32;
    int tx = threadIdx.x, ty = threadIdx.y;   // 32 x 8
#pragma unroll
    for (int i = 0; i < 4; i++) {
        int f = f0 + ty + i * 8;
        t[ty + i * 8][tx] = W[(size_t)r * Fd * Hd + (size_t)f * Hd + h0 + tx];
    }
    __syncthreads();
#pragma unroll
    for (int i = 0; i < 4; i++) {
        int h = h0 + ty + i * 8;
        float v = t[tx][ty + i * 8];
        __nv_bfloat16 hi = __float2bfloat16(v);
        __nv_bfloat16 lo = __float2bfloat16(v - __bfloat162float(hi));
        size_t oidx = (size_t)h * RH + r * Hd + f0 + tx;
        g_Wbh[oidx] = hi;
        g_Wbl[oidx] = lo;
    }
}

// ---------------- qx/kx + softmax-state init: warp per node ----------------
__global__ __launch_bounds__(256) void qxkx_kernel(const float* __restrict__ xin) {
    __shared__ float sq[Rr][Fd], sk[Rr][Fd];
    int tid = threadIdx.x;
    for (int i = tid; i < Rr * Fd; i += 256) {
        sq[i >> 7][i & 127] = g_Wq[i];
        sk[i >> 7][i & 127] = g_Wk[i];
    }
    __syncthreads();
    int w = tid >> 5, lane = tid & 31;
    int n = blockIdx.x * 8 + w;
    float4 xv = *(const float4*)&xin[(size_t)n * Fd + lane * 4];
#pragma unroll
    for (int r = 0; r < Rr; r++) {
        float4 q4 = *(const float4*)&sq[r][lane * 4];
        float4 k4 = *(const float4*)&sk[r][lane * 4];
        float qs = xv.x * q4.x + xv.y * q4.y + xv.z * q4.z + xv.w * q4.w;
        float ks = xv.x * k4.x + xv.y * k4.y + xv.z * k4.z + xv.w * k4.w;
#pragma unroll
        for (int o = 16; o; o >>= 1) {
            qs += __shfl_xor_sync(0xffffffffu, qs, o);
            ks += __shfl_xor_sync(0xffffffffu, ks, o);
        }
        if (lane == 0) { g_qx[n * Rr + r] = qs; g_kx[n * Rr + r] = ks; }
    }
    if (lane == 0) { g_mEnc[n] = 0u; g_s[n] = 0.f; }
}

// ---------------- edge-parallel scoring ----------------
__global__ void score_kernel() {
    int p = blockIdx.x * blockDim.x + threadIdx.x;
    if (p >= Ee) return;
    int src = g_esrc[p];
    int key = g_eky[p];
    int et  = key & 7;
    float a = g_qx[key] + g_kx[src * Rr + et];
    a = (a >= 0.f) ? a : 0.2f * a;
    g_ew[p] = a;
    atomicMax(&g_mEnc[key >> 3], encf(a));
}

__global__ void weight_kernel() {
    int p = blockIdx.x * blockDim.x + threadIdx.x;
    if (p >= Ee) return;
    int d = g_eky[p] >> 3;
    float w = __expf(g_ew[p] - decf(g_mEnc[d]));
    g_ew[p] = w;
    atomicAdd(&g_s[d], w);
}

// ---------------- aggregation: warp per dst, lane owns float4 of features ----------------
__global__ __launch_bounds__(256) void agg_kernel(const float* __restrict__ xin) {
    int wid = threadIdx.x >> 5, lane = threadIdx.x & 31;
    int d = blockIdx.x * 8 + wid;
    int b = 0;
    if (lane < 9) b = g_rp2[d * Rr + lane];
    float sv = g_s[d];
    float inv = (sv > 0.f) ? (1.f / sv) : 0.f;

#pragma unroll
    for (int r = 0; r < Rr; r++) {
        int beg = __shfl_sync(0xffffffffu, b, r);
        int end = __shfl_sync(0xffffffffu, b, r + 1);
        float4 acc = make_float4(0.f, 0.f, 0.f, 0.f);
        int j = beg;
        for (; j + 2 <= end; j += 2) {
            float w0 = __ldg(&g_ew[j]);
            float w1 = __ldg(&g_ew[j + 1]);
            int   s0 = __ldg(&g_esrc[j]);
            int   s1 = __ldg(&g_esrc[j + 1]);
            float4 x0 = *(const float4*)&xin[(size_t)s0 * Fd + lane * 4];
            float4 x1 = *(const float4*)&xin[(size_t)s1 * Fd + lane * 4];
            acc.x = fmaf(w0, x0.x, acc.x); acc.y = fmaf(w0, x0.y, acc.y);
            acc.z = fmaf(w0, x0.z, acc.z); acc.w = fmaf(w0, x0.w, acc.w);
            acc.x = fmaf(w1, x1.x, acc.x); acc.y = fmaf(w1, x1.y, acc.y);
            acc.z = fmaf(w1, x1.z, acc.z); acc.w = fmaf(w1, x1.w, acc.w);
        }
        if (j < end) {
            float w0 = __ldg(&g_ew[j]);
            int   s0 = __ldg(&g_esrc[j]);
            float4 x0 = *(const float4*)&xin[(size_t)s0 * Fd + lane * 4];
            acc.x = fmaf(w0, x0.x, acc.x); acc.y = fmaf(w0, x0.y, acc.y);
            acc.z = fmaf(w0, x0.z, acc.z); acc.w = fmaf(w0, x0.w, acc.w);
        }
        float v0 = acc.x * inv, v1 = acc.y * inv, v2 = acc.z * inv, v3 = acc.w * inv;
        __nv_bfloat16 h0 = __float2bfloat16(v0), h1 = __float2bfloat16(v1);
        __nv_bfloat16 h2 = __float2bfloat16(v2), h3 = __float2bfloat16(v3);
        __nv_bfloat16 l0 = __float2bfloat16(v0 - __bfloat162float(h0));
        __nv_bfloat16 l1 = __float2bfloat16(v1 - __bfloat162float(h1));
        __nv_bfloat16 l2 = __float2bfloat16(v2 - __bfloat162float(h2));
        __nv_bfloat16 l3 = __float2bfloat16(v3 - __bfloat162float(h3));
        __nv_bfloat162 ph0, ph1, pl0, pl1;
        ph0.x = h0; ph0.y = h1; ph1.x = h2; ph1.y = h3;
        pl0.x = l0; pl0.y = l1; pl1.x = l2; pl1.y = l3;
        uint2 sh, sl;
        sh.x = *(uint32_t*)&ph0; sh.y = *(uint32_t*)&ph1;
        sl.x = *(uint32_t*)&pl0; sl.y = *(uint32_t*)&pl1;
        size_t oidx = (size_t)d * RH + r * Hd + lane * 4;
        *(uint2*)&g_aggH[oidx] = sh;
        *(uint2*)&g_aggL[oidx] = sl;
    }
}

// ---------------- cp.async single-buffer bf16 3-pass GEMM, 2 CTAs/SM ----------------
#define KC 64
#define NKC (RH / KC)                 // 8
#define SSTR 72
#define STG_BYTES (128 * SSTR * 2)    // 18432
#define OFF_AH 0
#define OFF_AL STG_BYTES
#define OFF_BH (2 * STG_BYTES)
#define OFF_BL (3 * STG_BYTES)
#define SM_TOTAL (4 * STG_BYTES)      // 73728 -> 2 CTAs/SM

__global__ __launch_bounds__(256, 2) void gemm_mma_kernel(const float* __restrict__ bias,
                                                          float* __restrict__ hout) {
    extern __shared__ __align__(128) char smem[];
    const int tid = threadIdx.x, wid = tid >> 5, lane = tid & 31;
    const int row0 = blockIdx.x * 128;
    const int wr = wid >> 2, wc = wid & 3;
    const uint32_t sb = smem_u32(smem);

    float acc[4][4][4] = {};

    for (int kc = 0; kc < NKC; kc++) {
        const int kbase = kc * KC;
#pragma unroll
        for (int i = 0; i < 4; i++) {
            int cid = tid + i * 256;          // 0..1023
            int row = cid >> 3;               // 0..127
            int k8  = (cid & 7) * 8;          // 0..56
            uint32_t so = sb + (uint32_t)(row * SSTR + k8) * 2;
            int gr = row0 + row;
            int grc = (gr < Nn) ? gr : (Nn - 1);
            int sz = (gr < Nn) ? 16 : 0;
            size_t aidx = (size_t)grc * RH + kbase + k8;
            cp16(so + OFF_AH, &g_aggH[aidx], sz);
            cp16(so + OFF_AL, &g_aggL[aidx], sz);
            size_t bidx = (size_t)row * RH + kbase + k8;
            cp16(so + OFF_BH, &g_Wbh[bidx], 16);
            cp16(so + OFF_BL, &g_Wbl[bidx], 16);
        }
        asm volatile("cp.async.commit_group;");
        asm volatile("cp.async.wait_group 0;");
        __syncthreads();

#pragma unroll
        for (int ks = 0; ks < 4; ks++) {
            const int k0 = ks * 16;
            const uint32_t lrow = lane & 15;
            const uint32_t lcol = (k0 + ((lane >> 4) << 3)) * 2;
            uint32_t ah[4][4], al[4][4], bh[2][4], bl[2][4];
#pragma unroll
            for (int mt = 0; mt < 4; mt++) {
                uint32_t base = sb + (wr * 64 + mt * 16 + lrow) * (SSTR * 2) + lcol;
                ldsm_x4(ah[mt], base + OFF_AH);
                ldsm_x4(al[mt], base + OFF_AL);
            }
#pragma unroll
            for (int p = 0; p < 2; p++) {
                uint32_t base = sb + (wc * 32 + p * 16 + lrow) * (SSTR * 2) + lcol;
                ldsm_x4(bh[p], base + OFF_BH);
                ldsm_x4(bl[p], base + OFF_BL);
            }
#pragma unroll
            for (int mt = 0; mt < 4; mt++)
#pragma unroll
                for (int p = 0; p < 2; p++)
#pragma unroll
                    for (int q = 0; q < 2; q++) {
                        float* c = acc[mt][p * 2 + q];
                        mma_bf16(c, ah[mt], bh[p][q], bh[p][q + 2]);
                        mma_bf16(c, ah[mt], bl[p][q], bl[p][q + 2]);
                        mma_bf16(c, al[mt], bh[p][q], bh[p][q + 2]);
                    }
        }
        __syncthreads();
    }

    // stage accumulators -> smem (67584 B <= 73728)
    float (*stage)[132] = (float(*)[132])smem;
#pragma unroll
    for (int mt = 0; mt < 4; mt++)
#pragma unroll
        for (int nt = 0; nt < 4; nt++) {
            int rr = wr * 64 + mt * 16 + (lane >> 2);
            int cc = wc * 32 + nt * 8 + (lane & 3) * 2;
            stage[rr][cc]     = acc[mt][nt][0];
            stage[rr][cc + 1] = acc[mt][nt][1];
            stage[rr + 8][cc]     = acc[mt][nt][2];
            stage[rr + 8][cc + 1] = acc[mt][nt][3];
        }
    __syncthreads();

#pragma unroll
    for (int i = 0; i < 16; i++) {
        int cid = tid + i * 256;
        int row = cid >> 5;
        int c4  = (cid & 31) * 4;
        int node = row0 + row;
        if (node < Nn) {
            float4 v = *(const float4*)&stage[row][c4];
            v.x = fmaxf(v.x + __ldg(&bias[c4]),     0.f);
            v.y = fmaxf(v.y + __ldg(&bias[c4 + 1]), 0.f);
            v.z = fmaxf(v.z + __ldg(&bias[c4 + 2]), 0.f);
            v.w = fmaxf(v.w + __ldg(&bias[c4 + 3]), 0.f);
            *(float4*)&hout[(size_t)node * Hd + c4] = v;
        }
    }
}

// ---------------- final linear + log_softmax ----------------
__global__ __launch_bounds__(256) void final_kernel(const float* __restrict__ h,
                                                    const float* __restrict__ lw,
                                                    const float* __restrict__ lb,
                                                    float* __restrict__ out) {
    __shared__ float sh[8][Hd];
    int tid = threadIdx.x;
    int nodeBase = blockIdx.x * 8;
#pragma unroll
    for (int l = 0; l < 4; l++) {
        int idx = tid + l * 256;
        sh[idx >> 7][idx & 127] = h[(size_t)nodeBase * Hd + idx];
    }
    __syncthreads();
    int w = tid >> 5, lane = tid & 31;
    int n = nodeBase + w;
    float a0 = lb[lane], a1 = lb[lane + 32];
#pragma unroll 16
    for (int f = 0; f < Hd; f++) {
        float hv = sh[w][f];
        a0 = fmaf(hv, lw[f * Cc + lane], a0);
        a1 = fmaf(hv, lw[f * Cc + lane + 32], a1);
    }
    float mx = fmaxf(a0, a1);
#pragma unroll
    for (int o = 16; o; o >>= 1) mx = fmaxf(mx, __shfl_xor_sync(0xffffffffu, mx, o));
    float s = expf(a0 - mx) + expf(a1 - mx);
#pragma unroll
    for (int o = 16; o; o >>= 1) s += __shfl_xor_sync(0xffffffffu, s, o);
    float lse = mx + logf(s);
    out[(size_t)n * Cc + lane]      = a0 - lse;
    out[(size_t)n * Cc + lane + 32] = a1 - lse;
}

// ---------------- host orchestration ----------------
static void run_layer(const float* xin, const float* W, const float* q,
                      const float* k, const float* b, float* hout) {
    wqk_kernel<<<(Rr * Fd * 32 + 255) / 256, 256>>>(W, q, k);
    wprep_kernel<<<dim3(4, 4, 8), dim3(32, 8)>>>(W);
    qxkx_kernel<<<Nn / 8, 256>>>(xin);
    score_kernel<<<(Ee + 255) / 256, 256>>>();
    weight_kernel<<<(Ee + 255) / 256, 256>>>();
    agg_kernel<<<Nn / 8, 256>>>(xin);
    gemm_mma_kernel<<<(Nn + 127) / 128, 256, SM_TOTAL>>>(b, hout);
}

extern "C" void kernel_launch(void* const* d_in, const int* in_sizes, int n_in,
                              void* d_out, int out_size) {
    const float* x     = (const float*)d_in[0];
    const void*  ei    = d_in[1];
    const void*  et    = d_in[2];
    const float* W1    = (const float*)d_in[3];
    const float* q1    = (const float*)d_in[4];
    const float* k1    = (const float*)d_in[5];
    const float* b1    = (const float*)d_in[6];
    const float* W2    = (const float*)d_in[7];
    const float* q2    = (const float*)d_in[8];
    const float* k2    = (const float*)d_in[9];
    const float* b2    = (const float*)d_in[10];
    const float* W3    = (const float*)d_in[11];
    const float* q3    = (const float*)d_in[12];
    const float* k3    = (const float*)d_in[13];
    const float* b3    = (const float*)d_in[14];
    const float* lin_w = (const float*)d_in[15];
    const float* lin_b = (const float*)d_in[16];

    cudaFuncSetAttribute(gemm_mma_kernel,
                         cudaFuncAttributeMaxDynamicSharedMemorySize, SM_TOTAL);

    float *hA = nullptr, *hB = nullptr;
    cudaGetSymbolAddress((void**)&hA, g_hA);
    cudaGetSymbolAddress((void**)&hB, g_hB);

    detect_kernel<<<1, 32>>>((const unsigned*)ei);
    convert_kernel<<<(Ee + 255) / 256, 256>>>(ei, et);

    // CSR build keyed by (dst, et), once per launch
    zero_kernel<<<(NK + 255) / 256, 256>>>();
    hist_kernel<<<(Ee + 255) / 256, 256>>>();
    scan1_kernel<<<NB2, SCANB>>>();
    scan2_kernel<<<1, 1024>>>();
    scan3_kernel<<<(NK + 255) / 256, 256>>>();
    scatter_kernel<<<(Ee + 255) / 256, 256>>>();

    run_layer(x,  W1, q1, k1, b1, hA);
    run_layer(hA, W2, q2, k2, b2, hB);
    run_layer(hB, W3, q3, k3, b3, hA);

    final_kernel<<<Nn / 8, 256>>>(hA, lin_w, lin_b, (float*)d_out);
}

// round 9
// speedup vs baseline: 2.0546x; 1.2839x over previous
#include <cuda_runtime.h>
#include <cuda_bf16.h>
#include <cstdint>

#define Nn 50000
#define Ee 800000
#define Rr 8
#define Fd 128
#define Hd 128
#define Cc 64
#define RH (Rr * Hd)   // 1024
#define NK (Nn * Rr)   // 400000 segment keys
#define SCANB 512
#define NB2 ((NK + SCANB - 1) / SCANB)   // 782

// ---------------- device scratch ----------------
__device__ __nv_bfloat16 g_aggH[(size_t)Nn * RH];  // aggregated features (bf16)
__device__ float         g_hA[Nn * Hd];
__device__ float         g_hB[Nn * Hd];
__device__ float         g_qx[Nn * Rr];
__device__ float         g_kx[Nn * Rr];
__device__ __nv_bfloat16 g_Wbh[Hd * RH];   // Wcat [h][r*128+f] hi
__device__ __nv_bfloat16 g_Wbl[Hd * RH];   // lo
__device__ float         g_Wq[Rr * Fd];
__device__ float         g_Wk[Rr * Fd];
__device__ int           g_src[Ee];
__device__ int           g_dst[Ee];
__device__ int           g_et[Ee];
__device__ int           g_esrc[Ee];       // sorted by key = dst*8+et
__device__ int           g_eky[Ee];        // key per sorted slot
__device__ float         g_ew[Ee];         // score, then weight
__device__ unsigned      g_mEnc[Nn];
__device__ float         g_s[Nn];
__device__ int           g_rp2[NK + 1];
__device__ int           g_rpp[NK];
__device__ int           g_bsum[NB2];
__device__ int           g_cnt[NK];
__device__ int           g_fill[NK];
__device__ int           g_is64;

// ---------------- helpers ----------------
__device__ __forceinline__ unsigned encf(float f) {
    unsigned u = __float_as_uint(f);
    return (u & 0x80000000u) ? ~u : (u | 0x80000000u);
}
__device__ __forceinline__ float decf(unsigned u) {
    return (u & 0x80000000u) ? __uint_as_float(u & 0x7FFFFFFFu)
                             : __uint_as_float(~u);
}
__device__ __forceinline__ uint32_t smem_u32(const void* p) {
    uint32_t a;
    asm("{ .reg .u64 t; cvta.to.shared.u64 t, %1; cvt.u32.u64 %0, t; }" : "=r"(a) : "l"(p));
    return a;
}
__device__ __forceinline__ void ldsm_x4(uint32_t* r, uint32_t addr) {
    asm volatile("ldmatrix.sync.aligned.m8n8.x4.shared.b16 {%0,%1,%2,%3}, [%4];"
                 : "=r"(r[0]), "=r"(r[1]), "=r"(r[2]), "=r"(r[3]) : "r"(addr));
}
__device__ __forceinline__ void mma_bf16(float* c, const uint32_t* a, uint32_t b0, uint32_t b1) {
    asm volatile(
        "mma.sync.aligned.m16n8k16.row.col.f32.bf16.bf16.f32 "
        "{%0,%1,%2,%3}, {%4,%5,%6,%7}, {%8,%9}, {%0,%1,%2,%3};"
        : "+f"(c[0]), "+f"(c[1]), "+f"(c[2]), "+f"(c[3])
        : "r"(a[0]), "r"(a[1]), "r"(a[2]), "r"(a[3]), "r"(b0), "r"(b1));
}
__device__ __forceinline__ void cp16(uint32_t saddr, const void* g, int srcsize) {
    asm volatile("cp.async.cg.shared.global [%0], [%1], 16, %2;"
                 :: "r"(saddr), "l"(g), "r"(srcsize));
}

// ---------------- dtype detect + edge conversion ----------------
__global__ void detect_kernel(const unsigned* __restrict__ ei) {
    if (threadIdx.x == 0 && blockIdx.x == 0) {
        int zeros = 0;
        for (int i = 0; i < 128; i++)
            if (ei[2 * i + 1] == 0u) zeros++;
        g_is64 = (zeros == 128) ? 1 : 0;
    }
}

__global__ void convert_kernel(const void* __restrict__ ei, const void* __restrict__ et) {
    int e = blockIdx.x * blockDim.x + threadIdx.x;
    if (e >= Ee) return;
    if (g_is64) {
        const long long* p = (const long long*)ei;
        g_src[e] = (int)p[e];
        g_dst[e] = (int)p[Ee + e];
        g_et[e]  = (int)((const long long*)et)[e];
    } else {
        const int* p = (const int*)ei;
        g_src[e] = p[e];
        g_dst[e] = p[Ee + e];
        g_et[e]  = ((const int*)et)[e];
    }
}

// ---------------- CSR build keyed by (dst*8 + et) ----------------
__global__ void zero_kernel() {
    int i = blockIdx.x * blockDim.x + threadIdx.x;
    if (i < NK) { g_cnt[i] = 0; g_fill[i] = 0; }
}
__global__ void hist_kernel() {
    int e = blockIdx.x * blockDim.x + threadIdx.x;
    if (e < Ee) atomicAdd(&g_cnt[g_dst[e] * Rr + g_et[e]], 1);
}
__global__ void scan1_kernel() {
    __shared__ int ss[SCANB];
    int t = threadIdx.x;
    int idx = blockIdx.x * SCANB + t;
    int v = (idx < NK) ? g_cnt[idx] : 0;
    ss[t] = v;
    __syncthreads();
    for (int off = 1; off < SCANB; off <<= 1) {
        int tmp = (t >= off) ? ss[t - off] : 0;
        __syncthreads();
        ss[t] += tmp;
        __syncthreads();
    }
    if (idx < NK) g_rpp[idx] = ss[t] - v;
    if (t == SCANB - 1) g_bsum[blockIdx.x] = ss[t];
}
__global__ void scan2_kernel() {
    __shared__ int ss[1024];
    int t = threadIdx.x;
    int v = (t < NB2) ? g_bsum[t] : 0;
    ss[t] = v;
    __syncthreads();
    for (int off = 1; off < 1024; off <<= 1) {
        int tmp = (t >= off) ? ss[t - off] : 0;
        __syncthreads();
        ss[t] += tmp;
        __syncthreads();
    }
    if (t < NB2) g_bsum[t] = ss[t] - v;
    if (t == 1023) g_rp2[NK] = ss[t];
}
__global__ void scan3_kernel() {
    int idx = blockIdx.x * blockDim.x + threadIdx.x;
    if (idx < NK) g_rp2[idx] = g_rpp[idx] + g_bsum[idx >> 9];
}
__global__ void scatter_kernel() {
    int e = blockIdx.x * blockDim.x + threadIdx.x;
    if (e >= Ee) return;
    int key = g_dst[e] * Rr + g_et[e];
    int p = g_rp2[key] + atomicAdd(&g_fill[key], 1);
    g_esrc[p] = g_src[e];
    g_eky[p]  = key;
}

// ---------------- weight prep ----------------
__global__ void wqk_kernel(const float* __restrict__ W,
                           const float* __restrict__ q,
                           const float* __restrict__ k) {
    int warp = (blockIdx.x * blockDim.x + threadIdx.x) >> 5;
    int lane = threadIdx.x & 31;
    if (warp >= Rr * Fd) return;
    const float* wrow = W + (size_t)warp * Hd;
    float sq = 0.f, sk = 0.f;
#pragma unroll
    for (int j = 0; j < 4; j++) {
        float wv = wrow[lane + 32 * j];
        sq += wv * q[lane + 32 * j];
        sk += wv * k[lane + 32 * j];
    }
#pragma unroll
    for (int o = 16; o; o >>= 1) {
        sq += __shfl_xor_sync(0xffffffffu, sq, o);
        sk += __shfl_xor_sync(0xffffffffu, sk, o);
    }
    if (lane == 0) { g_Wq[warp] = sq; g_Wk[warp] = sk; }
}

__global__ void wprep_kernel(const float* __restrict__ W) {
    __shared__ float t[32][33];
    int r = blockIdx.z, f0 = blockIdx.x * 32, h0 = blockIdx.y * 32;
    int tx = threadIdx.x, ty = threadIdx.y;   // 32 x 8
#pragma unroll
    for (int i = 0; i < 4; i++) {
        int f = f0 + ty + i * 8;
        t[ty + i * 8][tx] = W[(size_t)r * Fd * Hd + (size_t)f * Hd + h0 + tx];
    }
    __syncthreads();
#pragma unroll
    for (int i = 0; i < 4; i++) {
        int h = h0 + ty + i * 8;
        float v = t[tx][ty + i * 8];
        __nv_bfloat16 hi = __float2bfloat16(v);
        __nv_bfloat16 lo = __float2bfloat16(v - __bfloat162float(hi));
        size_t oidx = (size_t)h * RH + r * Hd + f0 + tx;
        g_Wbh[oidx] = hi;
        g_Wbl[oidx] = lo;
    }
}

// ---------------- qx/kx + softmax-state init: warp per node ----------------
__global__ __launch_bounds__(256) void qxkx_kernel(const float* __restrict__ xin) {
    __shared__ float sq[Rr][Fd], sk[Rr][Fd];
    int tid = threadIdx.x;
    for (int i = tid; i < Rr * Fd; i += 256) {
        sq[i >> 7][i & 127] = g_Wq[i];
        sk[i >> 7][i & 127] = g_Wk[i];
    }
    __syncthreads();
    int w = tid >> 5, lane = tid & 31;
    int n = blockIdx.x * 8 + w;
    float4 xv = *(const float4*)&xin[(size_t)n * Fd + lane * 4];
#pragma unroll
    for (int r = 0; r < Rr; r++) {
        float4 q4 = *(const float4*)&sq[r][lane * 4];
        float4 k4 = *(const float4*)&sk[r][lane * 4];
        float qs = xv.x * q4.x + xv.y * q4.y + xv.z * q4.z + xv.w * q4.w;
        float ks = xv.x * k4.x + xv.y * k4.y + xv.z * k4.z + xv.w * k4.w;
#pragma unroll
        for (int o = 16; o; o >>= 1) {
            qs += __shfl_xor_sync(0xffffffffu, qs, o);
            ks += __shfl_xor_sync(0xffffffffu, ks, o);
        }
        if (lane == 0) { g_qx[n * Rr + r] = qs; g_kx[n * Rr + r] = ks; }
    }
    if (lane == 0) { g_mEnc[n] = 0u; g_s[n] = 0.f; }
}

// ---------------- edge-parallel scoring ----------------
__global__ void score_kernel() {
    int p = blockIdx.x * blockDim.x + threadIdx.x;
    if (p >= Ee) return;
    int src = g_esrc[p];
    int key = g_eky[p];
    int et  = key & 7;
    float a = g_qx[key] + g_kx[src * Rr + et];
    a = (a >= 0.f) ? a : 0.2f * a;
    g_ew[p] = a;
    atomicMax(&g_mEnc[key >> 3], encf(a));
}

__global__ void weight_kernel() {
    int p = blockIdx.x * blockDim.x + threadIdx.x;
    if (p >= Ee) return;
    int d = g_eky[p] >> 3;
    float w = __expf(g_ew[p] - decf(g_mEnc[d]));
    g_ew[p] = w;
    atomicAdd(&g_s[d], w);
}

// ---------------- aggregation: warp per dst, lane owns float4 of features ----------------
__global__ __launch_bounds__(256) void agg_kernel(const float* __restrict__ xin) {
    int wid = threadIdx.x >> 5, lane = threadIdx.x & 31;
    int d = blockIdx.x * 8 + wid;
    int b = 0;
    if (lane < 9) b = g_rp2[d * Rr + lane];
    float sv = g_s[d];
    float inv = (sv > 0.f) ? (1.f / sv) : 0.f;

#pragma unroll
    for (int r = 0; r < Rr; r++) {
        int beg = __shfl_sync(0xffffffffu, b, r);
        int end = __shfl_sync(0xffffffffu, b, r + 1);
        float4 acc = make_float4(0.f, 0.f, 0.f, 0.f);
        int j = beg;
        for (; j + 2 <= end; j += 2) {
            float w0 = __ldg(&g_ew[j]);
            float w1 = __ldg(&g_ew[j + 1]);
            int   s0 = __ldg(&g_esrc[j]);
            int   s1 = __ldg(&g_esrc[j + 1]);
            float4 x0 = *(const float4*)&xin[(size_t)s0 * Fd + lane * 4];
            float4 x1 = *(const float4*)&xin[(size_t)s1 * Fd + lane * 4];
            acc.x = fmaf(w0, x0.x, acc.x); acc.y = fmaf(w0, x0.y, acc.y);
            acc.z = fmaf(w0, x0.z, acc.z); acc.w = fmaf(w0, x0.w, acc.w);
            acc.x = fmaf(w1, x1.x, acc.x); acc.y = fmaf(w1, x1.y, acc.y);
            acc.z = fmaf(w1, x1.z, acc.z); acc.w = fmaf(w1, x1.w, acc.w);
        }
        if (j < end) {
            float w0 = __ldg(&g_ew[j]);
            int   s0 = __ldg(&g_esrc[j]);
            float4 x0 = *(const float4*)&xin[(size_t)s0 * Fd + lane * 4];
            acc.x = fmaf(w0, x0.x, acc.x); acc.y = fmaf(w0, x0.y, acc.y);
            acc.z = fmaf(w0, x0.z, acc.z); acc.w = fmaf(w0, x0.w, acc.w);
        }
        __nv_bfloat162 p0, p1;
        p0.x = __float2bfloat16(acc.x * inv);
        p0.y = __float2bfloat16(acc.y * inv);
        p1.x = __float2bfloat16(acc.z * inv);
        p1.y = __float2bfloat16(acc.w * inv);
        uint2 sh;
        sh.x = *(uint32_t*)&p0; sh.y = *(uint32_t*)&p1;
        *(uint2*)&g_aggH[(size_t)d * RH + r * Hd + lane * 4] = sh;
    }
}

// ---------------- cp.async double-buffered bf16 2-pass GEMM, 2 CTAs/SM ----------------
// h = relu(agg[N,1024](bf16) @ (Wh+Wl)^T + b);  C = Ah*Bh + Ah*Bl
#define KC 64
#define NKC (RH / KC)                 // 16
#define SSTR 72
#define STG_BYTES (128 * SSTR * 2)    // 18432
#define OFF_AH 0
#define OFF_BH STG_BYTES
#define OFF_BL (2 * STG_BYTES)
#define SM_STAGE (3 * STG_BYTES)      // 55296
#define SM_TOTAL (2 * SM_STAGE)       // 110592 -> 2 CTAs/SM (221 KB)

__global__ __launch_bounds__(256, 2) void gemm_mma_kernel(const float* __restrict__ bias,
                                                          float* __restrict__ hout) {
    extern __shared__ __align__(128) char smem[];
    const int tid = threadIdx.x, wid = tid >> 5, lane = tid & 31;
    const int row0 = blockIdx.x * 128;
    const int wr = wid >> 2, wc = wid & 3;
    const uint32_t sb = smem_u32(smem);

    float acc[4][4][4] = {};

    auto copy_chunk = [&](int kc, int buf) {
        const int kbase = kc * KC;
        const uint32_t sbase = sb + buf * SM_STAGE;
#pragma unroll
        for (int i = 0; i < 4; i++) {
            int cid = tid + i * 256;          // 0..1023
            int row = cid >> 3;               // 0..127
            int k8  = (cid & 7) * 8;          // 0..56
            uint32_t so = sbase + (uint32_t)(row * SSTR + k8) * 2;
            int gr = row0 + row;
            int grc = (gr < Nn) ? gr : (Nn - 1);
            int sz = (gr < Nn) ? 16 : 0;
            cp16(so + OFF_AH, &g_aggH[(size_t)grc * RH + kbase + k8], sz);
            size_t bidx = (size_t)row * RH + kbase + k8;
            cp16(so + OFF_BH, &g_Wbh[bidx], 16);
            cp16(so + OFF_BL, &g_Wbl[bidx], 16);
        }
        asm volatile("cp.async.commit_group;");
    };

    copy_chunk(0, 0);
    for (int kc = 0; kc < NKC; kc++) {
        const int buf = kc & 1;
        if (kc + 1 < NKC) {
            copy_chunk(kc + 1, buf ^ 1);
            asm volatile("cp.async.wait_group 1;");
        } else {
            asm volatile("cp.async.wait_group 0;");
        }
        __syncthreads();

        const uint32_t sbase = sb + buf * SM_STAGE;
#pragma unroll
        for (int ks = 0; ks < 4; ks++) {
            const int k0 = ks * 16;
            const uint32_t lrow = lane & 15;
            const uint32_t lcol = (k0 + ((lane >> 4) << 3)) * 2;
            uint32_t ah[4][4], bh[2][4], bl[2][4];
#pragma unroll
            for (int mt = 0; mt < 4; mt++) {
                uint32_t base = sbase + (wr * 64 + mt * 16 + lrow) * (SSTR * 2) + lcol;
                ldsm_x4(ah[mt], base + OFF_AH);
            }
#pragma unroll
            for (int p = 0; p < 2; p++) {
                uint32_t base = sbase + (wc * 32 + p * 16 + lrow) * (SSTR * 2) + lcol;
                ldsm_x4(bh[p], base + OFF_BH);
                ldsm_x4(bl[p], base + OFF_BL);
            }
#pragma unroll
            for (int mt = 0; mt < 4; mt++)
#pragma unroll
                for (int p = 0; p < 2; p++)
#pragma unroll
                    for (int q = 0; q < 2; q++) {
                        float* c = acc[mt][p * 2 + q];
                        mma_bf16(c, ah[mt], bh[p][q], bh[p][q + 2]);
                        mma_bf16(c, ah[mt], bl[p][q], bl[p][q + 2]);
                    }
        }
        __syncthreads();
    }

    // stage accumulators -> smem (67584 B <= 110592)
    float (*stage)[132] = (float(*)[132])smem;
#pragma unroll
    for (int mt = 0; mt < 4; mt++)
#pragma unroll
        for (int nt = 0; nt < 4; nt++) {
            int rr = wr * 64 + mt * 16 + (lane >> 2);
            int cc = wc * 32 + nt * 8 + (lane & 3) * 2;
            stage[rr][cc]     = acc[mt][nt][0];
            stage[rr][cc + 1] = acc[mt][nt][1];
            stage[rr + 8][cc]     = acc[mt][nt][2];
            stage[rr + 8][cc + 1] = acc[mt][nt][3];
        }
    __syncthreads();

#pragma unroll
    for (int i = 0; i < 16; i++) {
        int cid = tid + i * 256;
        int row = cid >> 5;
        int c4  = (cid & 31) * 4;
        int node = row0 + row;
        if (node < Nn) {
            float4 v = *(const float4*)&stage[row][c4];
            v.x = fmaxf(v.x + __ldg(&bias[c4]),     0.f);
            v.y = fmaxf(v.y + __ldg(&bias[c4 + 1]), 0.f);
            v.z = fmaxf(v.z + __ldg(&bias[c4 + 2]), 0.f);
            v.w = fmaxf(v.w + __ldg(&bias[c4 + 3]), 0.f);
            *(float4*)&hout[(size_t)node * Hd + c4] = v;
        }
    }
}

// ---------------- final linear + log_softmax ----------------
__global__ __launch_bounds__(256) void final_kernel(const float* __restrict__ h,
                                                    const float* __restrict__ lw,
                                                    const float* __restrict__ lb,
                                                    float* __restrict__ out) {
    __shared__ float sh[8][Hd];
    int tid = threadIdx.x;
    int nodeBase = blockIdx.x * 8;
#pragma unroll
    for (int l = 0; l < 4; l++) {
        int idx = tid + l * 256;
        sh[idx >> 7][idx & 127] = h[(size_t)nodeBase * Hd + idx];
    }
    __syncthreads();
    int w = tid >> 5, lane = tid & 31;
    int n = nodeBase + w;
    float a0 = lb[lane], a1 = lb[lane + 32];
#pragma unroll 16
    for (int f = 0; f < Hd; f++) {
        float hv = sh[w][f];
        a0 = fmaf(hv, lw[f * Cc + lane], a0);
        a1 = fmaf(hv, lw[f * Cc + lane + 32], a1);
    }
    float mx = fmaxf(a0, a1);
#pragma unroll
    for (int o = 16; o; o >>= 1) mx = fmaxf(mx, __shfl_xor_sync(0xffffffffu, mx, o));
    float s = expf(a0 - mx) + expf(a1 - mx);
#pragma unroll
    for (int o = 16; o; o >>= 1) s += __shfl_xor_sync(0xffffffffu, s, o);
    float lse = mx + logf(s);
    out[(size_t)n * Cc + lane]      = a0 - lse;
    out[(size_t)n * Cc + lane + 32] = a1 - lse;
}

// ---------------- host orchestration ----------------
static void run_layer(const float* xin, const float* W, const float* q,
                      const float* k, const float* b, float* hout) {
    wqk_kernel<<<(Rr * Fd * 32 + 255) / 256, 256>>>(W, q, k);
    wprep_kernel<<<dim3(4, 4, 8), dim3(32, 8)>>>(W);
    qxkx_kernel<<<Nn / 8, 256>>>(xin);
    score_kernel<<<(Ee + 255) / 256, 256>>>();
    weight_kernel<<<(Ee + 255) / 256, 256>>>();
    agg_kernel<<<Nn / 8, 256>>>(xin);
    gemm_mma_kernel<<<(Nn + 127) / 128, 256, SM_TOTAL>>>(b, hout);
}

extern "C" void kernel_launch(void* const* d_in, const int* in_sizes, int n_in,
                              void* d_out, int out_size) {
    const float* x     = (const float*)d_in[0];
    const void*  ei    = d_in[1];
    const void*  et    = d_in[2];
    const float* W1    = (const float*)d_in[3];
    const float* q1    = (const float*)d_in[4];
    const float* k1    = (const float*)d_in[5];
    const float* b1    = (const float*)d_in[6];
    const float* W2    = (const float*)d_in[7];
    const float* q2    = (const float*)d_in[8];
    const float* k2    = (const float*)d_in[9];
    const float* b2    = (const float*)d_in[10];
    const float* W3    = (const float*)d_in[11];
    const float* q3    = (const float*)d_in[12];
    const float* k3    = (const float*)d_in[13];
    const float* b3    = (const float*)d_in[14];
    const float* lin_w = (const float*)d_in[15];
    const float* lin_b = (const float*)d_in[16];

    cudaFuncSetAttribute(gemm_mma_kernel,
                         cudaFuncAttributeMaxDynamicSharedMemorySize, SM_TOTAL);

    float *hA = nullptr, *hB = nullptr;
    cudaGetSymbolAddress((void**)&hA, g_hA);
    cudaGetSymbolAddress((void**)&hB, g_hB);

    detect_kernel<<<1, 32>>>((const unsigned*)ei);
    convert_kernel<<<(Ee + 255) / 256, 256>>>(ei, et);

    // CSR build keyed by (dst, et), once per launch
    zero_kernel<<<(NK + 255) / 256, 256>>>();
    hist_kernel<<<(Ee + 255) / 256, 256>>>();
    scan1_kernel<<<NB2, SCANB>>>();
    scan2_kernel<<<1, 1024>>>();
    scan3_kernel<<<(NK + 255) / 256, 256>>>();
    scatter_kernel<<<(Ee + 255) / 256, 256>>>();

    run_layer(x,  W1, q1, k1, b1, hA);
    run_layer(hA, W2, q2, k2, b2, hB);
    run_layer(hB, W3, q3, k3, b3, hA);

    final_kernel<<<Nn / 8, 256>>>(hA, lin_w, lin_b, (float*)d_out);
}

// round 10
// speedup vs baseline: 2.4864x; 1.2101x over previous
#include <cuda_runtime.h>
#include <cuda_bf16.h>
#include <cstdint>

#define Nn 50000
#define Ee 800000
#define Rr 8
#define Fd 128
#define Hd 128
#define Cc 64
#define RH (Rr * Hd)   // 1024
#define NK (Nn * Rr)   // 400000 segment keys
#define SCANB 512
#define NB2 ((NK + SCANB - 1) / SCANB)   // 782

// ---------------- device scratch ----------------
__device__ __nv_bfloat16 g_aggH[(size_t)Nn * RH];  // aggregated features (bf16)
__device__ float         g_hA[Nn * Hd];
__device__ float         g_hB[Nn * Hd];
__device__ float         g_qx[Nn * Rr];
__device__ float         g_kx[Nn * Rr];
__device__ __nv_bfloat16 g_Wbh[Hd * RH];   // Wcat [h][r*128+f] bf16
__device__ float         g_Wq[Rr * Fd];
__device__ float         g_Wk[Rr * Fd];
__device__ int           g_src[Ee];
__device__ int           g_dst[Ee];
__device__ int           g_et[Ee];
__device__ int           g_esrc[Ee];       // sorted by key = dst*8+et
__device__ int           g_eky[Ee];        // key per sorted slot
__device__ float         g_ew[Ee];         // score, then weight
__device__ unsigned      g_mEnc[Nn];
__device__ float         g_s[Nn];
__device__ int           g_rp2[NK + 1];
__device__ int           g_rpp[NK];
__device__ int           g_bsum[NB2];
__device__ int           g_cnt[NK];
__device__ int           g_fill[NK];
__device__ int           g_is64;

// ---------------- helpers ----------------
__device__ __forceinline__ unsigned encf(float f) {
    unsigned u = __float_as_uint(f);
    return (u & 0x80000000u) ? ~u : (u | 0x80000000u);
}
__device__ __forceinline__ float decf(unsigned u) {
    return (u & 0x80000000u) ? __uint_as_float(u & 0x7FFFFFFFu)
                             : __uint_as_float(~u);
}
__device__ __forceinline__ uint32_t smem_u32(const void* p) {
    uint32_t a;
    asm("{ .reg .u64 t; cvta.to.shared.u64 t, %1; cvt.u32.u64 %0, t; }" : "=r"(a) : "l"(p));
    return a;
}
__device__ __forceinline__ void ldsm_x4(uint32_t* r, uint32_t addr) {
    asm volatile("ldmatrix.sync.aligned.m8n8.x4.shared.b16 {%0,%1,%2,%3}, [%4];"
                 : "=r"(r[0]), "=r"(r[1]), "=r"(r[2]), "=r"(r[3]) : "r"(addr));
}
__device__ __forceinline__ void mma_bf16(float* c, const uint32_t* a, uint32_t b0, uint32_t b1) {
    asm volatile(
        "mma.sync.aligned.m16n8k16.row.col.f32.bf16.bf16.f32 "
        "{%0,%1,%2,%3}, {%4,%5,%6,%7}, {%8,%9}, {%0,%1,%2,%3};"
        : "+f"(c[0]), "+f"(c[1]), "+f"(c[2]), "+f"(c[3])
        : "r"(a[0]), "r"(a[1]), "r"(a[2]), "r"(a[3]), "r"(b0), "r"(b1));
}
__device__ __forceinline__ void cp16(uint32_t saddr, const void* g, int srcsize) {
    asm volatile("cp.async.cg.shared.global [%0], [%1], 16, %2;"
                 :: "r"(saddr), "l"(g), "r"(srcsize));
}

// ---------------- dtype detect + edge conversion ----------------
__global__ void detect_kernel(const unsigned* __restrict__ ei) {
    if (threadIdx.x == 0 && blockIdx.x == 0) {
        int zeros = 0;
        for (int i = 0; i < 128; i++)
            if (ei[2 * i + 1] == 0u) zeros++;
        g_is64 = (zeros == 128) ? 1 : 0;
    }
}

__global__ void convert_kernel(const void* __restrict__ ei, const void* __restrict__ et) {
    int e = blockIdx.x * blockDim.x + threadIdx.x;
    if (e >= Ee) return;
    if (g_is64) {
        const long long* p = (const long long*)ei;
        g_src[e] = (int)p[e];
        g_dst[e] = (int)p[Ee + e];
        g_et[e]  = (int)((const long long*)et)[e];
    } else {
        const int* p = (const int*)ei;
        g_src[e] = p[e];
        g_dst[e] = p[Ee + e];
        g_et[e]  = ((const int*)et)[e];
    }
}

// ---------------- CSR build keyed by (dst*8 + et) ----------------
__global__ void zero_kernel() {
    int i = blockIdx.x * blockDim.x + threadIdx.x;
    if (i < NK) { g_cnt[i] = 0; g_fill[i] = 0; }
}
__global__ void hist_kernel() {
    int e = blockIdx.x * blockDim.x + threadIdx.x;
    if (e < Ee) atomicAdd(&g_cnt[g_dst[e] * Rr + g_et[e]], 1);
}
__global__ void scan1_kernel() {
    __shared__ int ss[SCANB];
    int t = threadIdx.x;
    int idx = blockIdx.x * SCANB + t;
    int v = (idx < NK) ? g_cnt[idx] : 0;
    ss[t] = v;
    __syncthreads();
    for (int off = 1; off < SCANB; off <<= 1) {
        int tmp = (t >= off) ? ss[t - off] : 0;
        __syncthreads();
        ss[t] += tmp;
        __syncthreads();
    }
    if (idx < NK) g_rpp[idx] = ss[t] - v;
    if (t == SCANB - 1) g_bsum[blockIdx.x] = ss[t];
}
__global__ void scan2_kernel() {
    __shared__ int ss[1024];
    int t = threadIdx.x;
    int v = (t < NB2) ? g_bsum[t] : 0;
    ss[t] = v;
    __syncthreads();
    for (int off = 1; off < 1024; off <<= 1) {
        int tmp = (t >= off) ? ss[t - off] : 0;
        __syncthreads();
        ss[t] += tmp;
        __syncthreads();
    }
    if (t < NB2) g_bsum[t] = ss[t] - v;
    if (t == 1023) g_rp2[NK] = ss[t];
}
__global__ void scan3_kernel() {
    int idx = blockIdx.x * blockDim.x + threadIdx.x;
    if (idx < NK) g_rp2[idx] = g_rpp[idx] + g_bsum[idx >> 9];
}
__global__ void scatter_kernel() {
    int e = blockIdx.x * blockDim.x + threadIdx.x;
    if (e >= Ee) return;
    int key = g_dst[e] * Rr + g_et[e];
    int p = g_rp2[key] + atomicAdd(&g_fill[key], 1);
    g_esrc[p] = g_src[e];
    g_eky[p]  = key;
}

// ---------------- weight prep ----------------
__global__ void wqk_kernel(const float* __restrict__ W,
                           const float* __restrict__ q,
                           const float* __restrict__ k) {
    int warp = (blockIdx.x * blockDim.x + threadIdx.x) >> 5;
    int lane = threadIdx.x & 31;
    if (warp >= Rr * Fd) return;
    const float* wrow = W + (size_t)warp * Hd;
    float sq = 0.f, sk = 0.f;
#pragma unroll
    for (int j = 0; j < 4; j++) {
        float wv = wrow[lane + 32 * j];
        sq += wv * q[lane + 32 * j];
        sk += wv * k[lane + 32 * j];
    }
#pragma unroll
    for (int o = 16; o; o >>= 1) {
        sq += __shfl_xor_sync(0xffffffffu, sq, o);
        sk += __shfl_xor_sync(0xffffffffu, sk, o);
    }
    if (lane == 0) { g_Wq[warp] = sq; g_Wk[warp] = sk; }
}

__global__ void wprep_kernel(const float* __restrict__ W) {
    __shared__ float t[32][33];
    int r = blockIdx.z, f0 = blockIdx.x * 32, h0 = blockIdx.y * 32;
    int tx = threadIdx.x, ty = threadIdx.y;   // 32 x 8
#pragma unroll
    for (int i = 0; i < 4; i++) {
        int f = f0 + ty + i * 8;
        t[ty + i * 8][tx] = W[(size_t)r * Fd * Hd + (size_t)f * Hd + h0 + tx];
    }
    __syncthreads();
#pragma unroll
    for (int i = 0; i < 4; i++) {
        int h = h0 + ty + i * 8;
        g_Wbh[(size_t)h * RH + r * Hd + f0 + tx] = __float2bfloat16(t[tx][ty + i * 8]);
    }
}

// ---------------- qx/kx + softmax-state init: warp per node ----------------
__global__ __launch_bounds__(256) void qxkx_kernel(const float* __restrict__ xin) {
    __shared__ float sq[Rr][Fd], sk[Rr][Fd];
    int tid = threadIdx.x;
    for (int i = tid; i < Rr * Fd; i += 256) {
        sq[i >> 7][i & 127] = g_Wq[i];
        sk[i >> 7][i & 127] = g_Wk[i];
    }
    __syncthreads();
    int w = tid >> 5, lane = tid & 31;
    int n = blockIdx.x * 8 + w;
    float4 xv = *(const float4*)&xin[(size_t)n * Fd + lane * 4];
#pragma unroll
    for (int r = 0; r < Rr; r++) {
        float4 q4 = *(const float4*)&sq[r][lane * 4];
        float4 k4 = *(const float4*)&sk[r][lane * 4];
        float qs = xv.x * q4.x + xv.y * q4.y + xv.z * q4.z + xv.w * q4.w;
        float ks = xv.x * k4.x + xv.y * k4.y + xv.z * k4.z + xv.w * k4.w;
#pragma unroll
        for (int o = 16; o; o >>= 1) {
            qs += __shfl_xor_sync(0xffffffffu, qs, o);
            ks += __shfl_xor_sync(0xffffffffu, ks, o);
        }
        if (lane == 0) { g_qx[n * Rr + r] = qs; g_kx[n * Rr + r] = ks; }
    }
    if (lane == 0) { g_mEnc[n] = 0u; g_s[n] = 0.f; }
}

// ---------------- edge-parallel scoring ----------------
__global__ void score_kernel() {
    int p = blockIdx.x * blockDim.x + threadIdx.x;
    if (p >= Ee) return;
    int src = g_esrc[p];
    int key = g_eky[p];
    int et  = key & 7;
    float a = g_qx[key] + g_kx[src * Rr + et];
    a = (a >= 0.f) ? a : 0.2f * a;
    g_ew[p] = a;
    atomicMax(&g_mEnc[key >> 3], encf(a));
}

__global__ void weight_kernel() {
    int p = blockIdx.x * blockDim.x + threadIdx.x;
    if (p >= Ee) return;
    int d = g_eky[p] >> 3;
    float w = __expf(g_ew[p] - decf(g_mEnc[d]));
    g_ew[p] = w;
    atomicAdd(&g_s[d], w);
}

// ---------------- aggregation: warp per dst, lane owns float4 of features ----------------
__global__ __launch_bounds__(256) void agg_kernel(const float* __restrict__ xin) {
    int wid = threadIdx.x >> 5, lane = threadIdx.x & 31;
    int d = blockIdx.x * 8 + wid;
    int b = 0;
    if (lane < 9) b = g_rp2[d * Rr + lane];
    float sv = g_s[d];
    float inv = (sv > 0.f) ? (1.f / sv) : 0.f;

#pragma unroll
    for (int r = 0; r < Rr; r++) {
        int beg = __shfl_sync(0xffffffffu, b, r);
        int end = __shfl_sync(0xffffffffu, b, r + 1);
        float4 acc = make_float4(0.f, 0.f, 0.f, 0.f);
        int j = beg;
        for (; j + 2 <= end; j += 2) {
            float w0 = __ldg(&g_ew[j]);
            float w1 = __ldg(&g_ew[j + 1]);
            int   s0 = __ldg(&g_esrc[j]);
            int   s1 = __ldg(&g_esrc[j + 1]);
            float4 x0 = *(const float4*)&xin[(size_t)s0 * Fd + lane * 4];
            float4 x1 = *(const float4*)&xin[(size_t)s1 * Fd + lane * 4];
            acc.x = fmaf(w0, x0.x, acc.x); acc.y = fmaf(w0, x0.y, acc.y);
            acc.z = fmaf(w0, x0.z, acc.z); acc.w = fmaf(w0, x0.w, acc.w);
            acc.x = fmaf(w1, x1.x, acc.x); acc.y = fmaf(w1, x1.y, acc.y);
            acc.z = fmaf(w1, x1.z, acc.z); acc.w = fmaf(w1, x1.w, acc.w);
        }
        if (j < end) {
            float w0 = __ldg(&g_ew[j]);
            int   s0 = __ldg(&g_esrc[j]);
            float4 x0 = *(const float4*)&xin[(size_t)s0 * Fd + lane * 4];
            acc.x = fmaf(w0, x0.x, acc.x); acc.y = fmaf(w0, x0.y, acc.y);
            acc.z = fmaf(w0, x0.z, acc.z); acc.w = fmaf(w0, x0.w, acc.w);
        }
        __nv_bfloat162 p0, p1;
        p0.x = __float2bfloat16(acc.x * inv);
        p0.y = __float2bfloat16(acc.y * inv);
        p1.x = __float2bfloat16(acc.z * inv);
        p1.y = __float2bfloat16(acc.w * inv);
        uint2 sh;
        sh.x = *(uint32_t*)&p0; sh.y = *(uint32_t*)&p1;
        *(uint2*)&g_aggH[(size_t)d * RH + r * Hd + lane * 4] = sh;
    }
}

// ---------------- cp.async double-buffered bf16 single-pass GEMM, 2 CTAs/SM ----------------
// h = relu(agg[N,1024](bf16) @ Wbh^T + b)
#define KC 64
#define NKC (RH / KC)                 // 16
#define SSTR 72
#define STG_BYTES (128 * SSTR * 2)    // 18432
#define OFF_AH 0
#define OFF_BH STG_BYTES
#define SM_STAGE (2 * STG_BYTES)      // 36864
#define SM_TOTAL (2 * SM_STAGE)       // 73728 -> 2 CTAs/SM

__global__ __launch_bounds__(256, 2) void gemm_mma_kernel(const float* __restrict__ bias,
                                                          float* __restrict__ hout) {
    extern __shared__ __align__(128) char smem[];
    const int tid = threadIdx.x, wid = tid >> 5, lane = tid & 31;
    const int row0 = blockIdx.x * 128;
    const int wr = wid >> 2, wc = wid & 3;
    const uint32_t sb = smem_u32(smem);

    float acc[4][4][4] = {};

    auto copy_chunk = [&](int kc, int buf) {
        const int kbase = kc * KC;
        const uint32_t sbase = sb + buf * SM_STAGE;
#pragma unroll
        for (int i = 0; i < 4; i++) {
            int cid = tid + i * 256;          // 0..1023
            int row = cid >> 3;               // 0..127
            int k8  = (cid & 7) * 8;          // 0..56
            uint32_t so = sbase + (uint32_t)(row * SSTR + k8) * 2;
            int gr = row0 + row;
            int grc = (gr < Nn) ? gr : (Nn - 1);
            int sz = (gr < Nn) ? 16 : 0;
            cp16(so + OFF_AH, &g_aggH[(size_t)grc * RH + kbase + k8], sz);
            cp16(so + OFF_BH, &g_Wbh[(size_t)row * RH + kbase + k8], 16);
        }
        asm volatile("cp.async.commit_group;");
    };

    copy_chunk(0, 0);
    for (int kc = 0; kc < NKC; kc++) {
        const int buf = kc & 1;
        if (kc + 1 < NKC) {
            copy_chunk(kc + 1, buf ^ 1);
            asm volatile("cp.async.wait_group 1;");
        } else {
            asm volatile("cp.async.wait_group 0;");
        }
        __syncthreads();

        const uint32_t sbase = sb + buf * SM_STAGE;
#pragma unroll
        for (int ks = 0; ks < 4; ks++) {
            const int k0 = ks * 16;
            const uint32_t lrow = lane & 15;
            const uint32_t lcol = (k0 + ((lane >> 4) << 3)) * 2;
            uint32_t ah[4][4], bh[2][4];
#pragma unroll
            for (int mt = 0; mt < 4; mt++) {
                uint32_t base = sbase + (wr * 64 + mt * 16 + lrow) * (SSTR * 2) + lcol;
                ldsm_x4(ah[mt], base + OFF_AH);
            }
#pragma unroll
            for (int p = 0; p < 2; p++) {
                uint32_t base = sbase + (wc * 32 + p * 16 + lrow) * (SSTR * 2) + lcol;
                ldsm_x4(bh[p], base + OFF_BH);
            }
#pragma unroll
            for (int mt = 0; mt < 4; mt++)
#pragma unroll
                for (int p = 0; p < 2; p++)
#pragma unroll
                    for (int q = 0; q < 2; q++)
                        mma_bf16(acc[mt][p * 2 + q], ah[mt], bh[p][q], bh[p][q + 2]);
        }
        __syncthreads();
    }

    // stage accumulators -> smem (67584 B <= 73728)
    float (*stage)[132] = (float(*)[132])smem;
#pragma unroll
    for (int mt = 0; mt < 4; mt++)
#pragma unroll
        for (int nt = 0; nt < 4; nt++) {
            int rr = wr * 64 + mt * 16 + (lane >> 2);
            int cc = wc * 32 + nt * 8 + (lane & 3) * 2;
            stage[rr][cc]     = acc[mt][nt][0];
            stage[rr][cc + 1] = acc[mt][nt][1];
            stage[rr + 8][cc]     = acc[mt][nt][2];
            stage[rr + 8][cc + 1] = acc[mt][nt][3];
        }
    __syncthreads();

#pragma unroll
    for (int i = 0; i < 16; i++) {
        int cid = tid + i * 256;
        int row = cid >> 5;
        int c4  = (cid & 31) * 4;
        int node = row0 + row;
        if (node < Nn) {
            float4 v = *(const float4*)&stage[row][c4];
            v.x = fmaxf(v.x + __ldg(&bias[c4]),     0.f);
            v.y = fmaxf(v.y + __ldg(&bias[c4 + 1]), 0.f);
            v.z = fmaxf(v.z + __ldg(&bias[c4 + 2]), 0.f);
            v.w = fmaxf(v.w + __ldg(&bias[c4 + 3]), 0.f);
            *(float4*)&hout[(size_t)node * Hd + c4] = v;
        }
    }
}

// ---------------- final linear + log_softmax ----------------
__global__ __launch_bounds__(256) void final_kernel(const float* __restrict__ h,
                                                    const float* __restrict__ lw,
                                                    const float* __restrict__ lb,
                                                    float* __restrict__ out) {
    __shared__ float sh[8][Hd];
    int tid = threadIdx.x;
    int nodeBase = blockIdx.x * 8;
#pragma unroll
    for (int l = 0; l < 4; l++) {
        int idx = tid + l * 256;
        sh[idx >> 7][idx & 127] = h[(size_t)nodeBase * Hd + idx];
    }
    __syncthreads();
    int w = tid >> 5, lane = tid & 31;
    int n = nodeBase + w;
    float a0 = lb[lane], a1 = lb[lane + 32];
#pragma unroll 16
    for (int f = 0; f < Hd; f++) {
        float hv = sh[w][f];
        a0 = fmaf(hv, lw[f * Cc + lane], a0);
        a1 = fmaf(hv, lw[f * Cc + lane + 32], a1);
    }
    float mx = fmaxf(a0, a1);
#pragma unroll
    for (int o = 16; o; o >>= 1) mx = fmaxf(mx, __shfl_xor_sync(0xffffffffu, mx, o));
    float s = expf(a0 - mx) + expf(a1 - mx);
#pragma unroll
    for (int o = 16; o; o >>= 1) s += __shfl_xor_sync(0xffffffffu, s, o);
    float lse = mx + logf(s);
    out[(size_t)n * Cc + lane]      = a0 - lse;
    out[(size_t)n * Cc + lane + 32] = a1 - lse;
}

// ---------------- host orchestration ----------------
static void run_layer(const float* xin, const float* W, const float* q,
                      const float* k, const float* b, float* hout) {
    wqk_kernel<<<(Rr * Fd * 32 + 255) / 256, 256>>>(W, q, k);
    wprep_kernel<<<dim3(4, 4, 8), dim3(32, 8)>>>(W);
    qxkx_kernel<<<Nn / 8, 256>>>(xin);
    score_kernel<<<(Ee + 255) / 256, 256>>>();
    weight_kernel<<<(Ee + 255) / 256, 256>>>();
    agg_kernel<<<Nn / 8, 256>>>(xin);
    gemm_mma_kernel<<<(Nn + 127) / 128, 256, SM_TOTAL>>>(b, hout);
}

extern "C" void kernel_launch(void* const* d_in, const int* in_sizes, int n_in,
                              void* d_out, int out_size) {
    const float* x     = (const float*)d_in[0];
    const void*  ei    = d_in[1];
    const void*  et    = d_in[2];
    const float* W1    = (const float*)d_in[3];
    const float* q1    = (const float*)d_in[4];
    const float* k1    = (const float*)d_in[5];
    const float* b1    = (const float*)d_in[6];
    const float* W2    = (const float*)d_in[7];
    const float* q2    = (const float*)d_in[8];
    const float* k2    = (const float*)d_in[9];
    const float* b2    = (const float*)d_in[10];
    const float* W3    = (const float*)d_in[11];
    const float* q3    = (const float*)d_in[12];
    const float* k3    = (const float*)d_in[13];
    const float* b3    = (const float*)d_in[14];
    const float* lin_w = (const float*)d_in[15];
    const float* lin_b = (const float*)d_in[16];

    cudaFuncSetAttribute(gemm_mma_kernel,
                         cudaFuncAttributeMaxDynamicSharedMemorySize, SM_TOTAL);

    float *hA = nullptr, *hB = nullptr;
    cudaGetSymbolAddress((void**)&hA, g_hA);
    cudaGetSymbolAddress((void**)&hB, g_hB);

    detect_kernel<<<1, 32>>>((const unsigned*)ei);
    convert_kernel<<<(Ee + 255) / 256, 256>>>(ei, et);

    // CSR build keyed by (dst, et), once per launch
    zero_kernel<<<(NK + 255) / 256, 256>>>();
    hist_kernel<<<(Ee + 255) / 256, 256>>>();
    scan1_kernel<<<NB2, SCANB>>>();
    scan2_kernel<<<1, 1024>>>();
    scan3_kernel<<<(NK + 255) / 256, 256>>>();
    scatter_kernel<<<(Ee + 255) / 256, 256>>>();

    run_layer(x,  W1, q1, k1, b1, hA);
    run_layer(hA, W2, q2, k2, b2, hB);
    run_layer(hB, W3, q3, k3, b3, hA);

    final_kernel<<<Nn / 8, 256>>>(hA, lin_w, lin_b, (float*)d_out);
}